// round 9
// baseline (speedup 1.0000x reference)
#include <cuda_runtime.h>
#include <cuda_fp16.h>
#include <math.h>
#include <stdint.h>

#define Bb 2
#define Nn 2048
#define EMB 768
#define NH 12
#define DH 64
#define DEPTH 6
#define FF 3072
#define TOK (Bb * Nn)  // 4096
#define LN_EPS 1e-6f

// ---------------- scratch (static device globals) ---------------------------
__device__ float g_h[TOK * EMB];          // residual stream (fp32)
__device__ __half g_y[TOK * EMB];         // LN output (fp16)
__device__ float g_qkv[TOK * 3 * EMB];    // qkv (fp32, attention input)
__device__ __half g_o[TOK * EMB];         // attention output (fp16)
__device__ __half g_mid[TOK * FF];        // FFN hidden (fp16)
// transposed + fp16 weights ([Nout][K], K-major rows)
__device__ __half g_wqkv[DEPTH * EMB * 3 * EMB];
__device__ __half g_wo[DEPTH * EMB * EMB];
__device__ __half g_w1[DEPTH * EMB * FF];
__device__ __half g_w2[DEPTH * FF * EMB];

__constant__ float c_slopes[NH] = {
    0.5f, 0.25f, 0.125f, 0.0625f, 0.03125f, 0.015625f, 0.0078125f, 0.00390625f,
    0.70710678118654752f, 0.35355339059327376f, 0.17677669529663688f,
    0.08838834764831844f};

__device__ __forceinline__ void cp16(uint32_t dst, const void* src) {
    asm volatile("cp.async.ca.shared.global [%0], [%1], 16;" ::"r"(dst),
                 "l"(src));
}

#define MMA_FP16(d, a, b)                                                     \
    asm volatile(                                                             \
        "mma.sync.aligned.m16n8k16.row.col.f32.f16.f16.f32 "                  \
        "{%0,%1,%2,%3},{%4,%5,%6,%7},{%8,%9},{%0,%1,%2,%3};"                  \
        : "+f"(d[0]), "+f"(d[1]), "+f"(d[2]), "+f"(d[3])                      \
        : "r"(a[0]), "r"(a[1]), "r"(a[2]), "r"(a[3]), "r"(b[0]), "r"(b[1]))

#define LDSM_X4(r0, r1, r2, r3, addr)                                        \
    asm volatile(                                                            \
        "ldmatrix.sync.aligned.m8n8.x4.shared.b16 {%0,%1,%2,%3}, [%4];"      \
        : "=r"(r0), "=r"(r1), "=r"(r2), "=r"(r3)                             \
        : "r"(addr))

// ---------------- copy x -> h ------------------------------------------------
__global__ void copy_kernel(const float* __restrict__ x) {
    int i = blockIdx.x * blockDim.x + threadIdx.x;
    if (i < TOK * EMB) g_h[i] = x[i];
}

// ---------------- fused transpose + fp16 convert of ALL weights -------------
#define TQKV (72 * 24 * DEPTH)
#define TWO (24 * 24 * DEPTH)
#define TW1 (96 * 24 * DEPTH)
#define TW2 (24 * 96 * DEPTH)
#define TALL (TQKV + TWO + TW1 + TW2)

__global__ void transpose_half_all(const float* __restrict__ wqkv,
                                   const float* __restrict__ wo,
                                   const float* __restrict__ w1,
                                   const float* __restrict__ w2,
                                   __half* __restrict__ pwqkv,
                                   __half* __restrict__ pwo,
                                   __half* __restrict__ pw1,
                                   __half* __restrict__ pw2) {
    __shared__ float tile[32][33];
    int b = blockIdx.x;
    const float* W;
    __half* Wt;
    int K, N;
    if (b < TQKV) {
        W = wqkv; Wt = pwqkv; K = EMB; N = 3 * EMB;
    } else if (b < TQKV + TWO) {
        b -= TQKV; W = wo; Wt = pwo; K = EMB; N = EMB;
    } else if (b < TQKV + TWO + TW1) {
        b -= TQKV + TWO; W = w1; Wt = pw1; K = EMB; N = FF;
    } else {
        b -= TQKV + TWO + TW1; W = w2; Wt = pw2; K = FF; N = EMB;
    }
    int ntiles = N / 32, tpl = ntiles * (K / 32);
    int layer = b / tpl, rem = b % tpl;
    int bn = (rem % ntiles) * 32, bk = (rem / ntiles) * 32;
    W += (size_t)layer * K * N;
    Wt += (size_t)layer * K * N;
    int tx = threadIdx.x, ty = threadIdx.y;
#pragma unroll
    for (int i = 0; i < 32; i += 8)
        tile[ty + i][tx] = W[(size_t)(bk + ty + i) * N + bn + tx];
    __syncthreads();
#pragma unroll
    for (int i = 0; i < 32; i += 8)
        Wt[(size_t)(bn + ty + i) * K + bk + tx] =
            __float2half_rn(tile[tx][ty + i]);
}

// ---------------- LayerNorm (float in; float or half out) -------------------
__global__ void ln_kernel(const float* __restrict__ in,
                          const float* __restrict__ scale,
                          const float* __restrict__ bias, void* __restrict__ o,
                          int half_out) {
    int row = blockIdx.x;
    const float* p = in + (size_t)row * EMB;
    float s = 0.f, ss = 0.f;
    for (int i = threadIdx.x; i < EMB; i += 256) {
        float v = p[i];
        s += v;
        ss += v * v;
    }
#pragma unroll
    for (int of = 16; of; of >>= 1) {
        s += __shfl_xor_sync(0xffffffffu, s, of);
        ss += __shfl_xor_sync(0xffffffffu, ss, of);
    }
    __shared__ float sh_s[8], sh_ss[8];
    int w = threadIdx.x >> 5, lane = threadIdx.x & 31;
    if (lane == 0) { sh_s[w] = s; sh_ss[w] = ss; }
    __syncthreads();
    if (threadIdx.x < 32) {
        s = (lane < 8) ? sh_s[lane] : 0.f;
        ss = (lane < 8) ? sh_ss[lane] : 0.f;
#pragma unroll
        for (int of = 4; of; of >>= 1) {
            s += __shfl_xor_sync(0xffffffffu, s, of);
            ss += __shfl_xor_sync(0xffffffffu, ss, of);
        }
        if (lane == 0) { sh_s[0] = s; sh_ss[0] = ss; }
    }
    __syncthreads();
    float mean = sh_s[0] * (1.0f / EMB);
    float var = sh_ss[0] * (1.0f / EMB) - mean * mean;
    float inv = rsqrtf(var + LN_EPS);
    if (half_out) {
        __half* q = (__half*)o + (size_t)row * EMB;
        for (int i = threadIdx.x; i < EMB; i += 256)
            q[i] = __float2half_rn((p[i] - mean) * inv * scale[i] + bias[i]);
    } else {
        float* q = (float*)o + (size_t)row * EMB;
        for (int i = threadIdx.x; i < EMB; i += 256)
            q[i] = (p[i] - mean) * inv * scale[i] + bias[i];
    }
}

// ---------------- fp16 mma.sync GEMM: CTA 128x64, 4 warps, 4 CTA/SM ---------
// C[M,Nout] = A[M,K] @ Wt[Nout,K]^T  (+bias, +gelu, +=C, half-out)
#define FLAG_BIAS 1
#define FLAG_GELU 2
#define FLAG_ADD 4
#define FLAG_HALF 8

#define STAGES 4
#define A_STAGE 8192                // 128 rows x 64B
#define B_STAGE 4096                // 64 rows x 64B
#define STAGE_BYTES (A_STAGE + B_STAGE)
#define GEMM_SMEM (STAGES * STAGE_BYTES)

__device__ __forceinline__ float gelu_tanh(float x) {
    const float k0 = 0.7978845608028654f;
    return 0.5f * x * (1.0f + tanhf(k0 * (x + 0.044715f * x * x * x)));
}

__global__ __launch_bounds__(128, 4) void gemm_fp16(
    const __half* __restrict__ A, const __half* __restrict__ Wt,
    const float* __restrict__ bias, void* __restrict__ Cv, int K, int Nout,
    int flags) {
    extern __shared__ char smem[];
    const uint32_t sb = (uint32_t)__cvta_generic_to_shared(smem);
    const int tid = threadIdx.x;
    const int warp = tid >> 5, lane = tid & 31;
    const int wm = warp >> 1, wn = warp & 1;  // 2m x 2n warps
    const int bm = blockIdx.y * 128, bn = blockIdx.x * 64;

    // ---- staging: A row `tid` (4 x 16B); B row tid>>1, half (tid&1) -------
    const __half* gA = A + (size_t)(bm + tid) * K;
    const int brow = tid >> 1, bc0 = (tid & 1) * 2;
    const __half* gB = Wt + (size_t)(bn + brow) * K + bc0 * 8;
    uint32_t stA[4], stB[2];
#pragma unroll
    for (int c = 0; c < 4; c++)
        stA[c] = sb + (uint32_t)tid * 64 +
                 (((uint32_t)(c ^ ((tid >> 1) & 3))) << 4);
#pragma unroll
    for (int i = 0; i < 2; i++)
        stB[i] = sb + A_STAGE + (uint32_t)brow * 64 +
                 (((uint32_t)((bc0 + i) ^ ((brow >> 1) & 3))) << 4);

#define LOAD_STAGE(s, t_)                                                  \
    do {                                                                   \
        const __half* _a = gA + (t_) * 32;                                 \
        const __half* _b = gB + (t_) * 32;                                 \
        uint32_t _so = (uint32_t)(s)*STAGE_BYTES;                          \
        _Pragma("unroll") for (int _c = 0; _c < 4; _c++)                   \
            cp16(stA[_c] + _so, _a + _c * 8);                              \
        _Pragma("unroll") for (int _i = 0; _i < 2; _i++)                   \
            cp16(stB[_i] + _so, _b + _i * 8);                              \
        asm volatile("cp.async.commit_group;");                            \
    } while (0)

    // ---- A fragment ldmatrix addresses (m16n8k16, x4) ----------------------
    // lanes 0-7: rows 0-7 chunk lo; 8-15: rows 8-15 chunk lo;
    // lanes 16-23: rows 0-7 chunk hi; 24-31: rows 8-15 chunk hi
    int arow7 = lane & 7;
    int a8 = ((lane >> 3) & 1) * 8;
    int acbit = lane >> 4;
    int axor = (arow7 >> 1) & 3;  // higher row bits don't affect (r>>1)&3
    uint32_t aBase[4];
#pragma unroll
    for (int mf = 0; mf < 4; mf++) {
        int r = wm * 64 + mf * 16 + arow7 + a8;
        aBase[mf] = sb + (uint32_t)r * 64;
    }
    uint32_t aoff[2];
#pragma unroll
    for (int ks = 0; ks < 2; ks++)
        aoff[ks] = ((uint32_t)((2 * ks + acbit) ^ axor)) << 4;

    // ---- B fragment addresses: x4 loads 2 n-frags (b0,b1 each) ------------
    // lanes 0-7: rows n0-7 chunk lo; 8-15: n0-7 chunk hi;
    // lanes 16-23: n8-15 chunk lo; 24-31: n8-15 chunk hi
    int brow7 = lane & 7;
    int bn8 = (lane >> 4) * 8;
    int bcb = (lane >> 3) & 1;
    int bxor = (brow7 >> 1) & 3;
    uint32_t bBase[2];
#pragma unroll
    for (int p = 0; p < 2; p++) {
        int r = wn * 32 + p * 16 + brow7 + bn8;
        bBase[p] = sb + A_STAGE + (uint32_t)r * 64;
    }
    uint32_t boff[2];
#pragma unroll
    for (int ks = 0; ks < 2; ks++)
        boff[ks] = ((uint32_t)((2 * ks + bcb) ^ bxor)) << 4;

    float acc[4][4][4];
#pragma unroll
    for (int i = 0; i < 4; i++)
#pragma unroll
        for (int j = 0; j < 4; j++)
#pragma unroll
            for (int c = 0; c < 4; c++) acc[i][j][c] = 0.f;

    const int T = K / 32;

    LOAD_STAGE(0, 0);
    LOAD_STAGE(1, 1);
    LOAD_STAGE(2, 2);

    for (int t = 0; t < T; t++) {
        int rem = ((t + 2 < T) ? (t + 2) : (T - 1)) - t;
        if (rem == 2)
            asm volatile("cp.async.wait_group 2;");
        else if (rem == 1)
            asm volatile("cp.async.wait_group 1;");
        else
            asm volatile("cp.async.wait_group 0;");
        __syncthreads();
        if (t + 3 < T) LOAD_STAGE((t + 3) & 3, t + 3);

        uint32_t so = (uint32_t)(t & 3) * STAGE_BYTES;
#pragma unroll
        for (int ks = 0; ks < 2; ks++) {
            uint32_t af[4][4], bf[4][2];
#pragma unroll
            for (int mf = 0; mf < 4; mf++)
                LDSM_X4(af[mf][0], af[mf][1], af[mf][2], af[mf][3],
                        aBase[mf] + so + aoff[ks]);
#pragma unroll
            for (int p = 0; p < 2; p++)
                LDSM_X4(bf[2 * p][0], bf[2 * p][1], bf[2 * p + 1][0],
                        bf[2 * p + 1][1], bBase[p] + so + boff[ks]);
#pragma unroll
            for (int mf = 0; mf < 4; mf++)
#pragma unroll
                for (int nf = 0; nf < 4; nf++)
                    MMA_FP16(acc[mf][nf], af[mf], bf[nf]);
        }
    }

    // ---- epilogue ----
    int r = lane >> 2, kq = lane & 3;
#pragma unroll
    for (int mf = 0; mf < 4; mf++) {
#pragma unroll
        for (int nf = 0; nf < 4; nf++) {
            int n0 = bn + wn * 32 + nf * 8 + kq * 2;
#pragma unroll
            for (int half = 0; half < 2; half++) {
                int m0 = bm + wm * 64 + mf * 16 + r + half * 8;
                float2 v;
                v.x = acc[mf][nf][half * 2 + 0];
                v.y = acc[mf][nf][half * 2 + 1];
                if (flags & FLAG_BIAS) {
                    v.x += bias[n0];
                    v.y += bias[n0 + 1];
                }
                if (flags & FLAG_GELU) {
                    v.x = gelu_tanh(v.x);
                    v.y = gelu_tanh(v.y);
                }
                if (flags & FLAG_HALF) {
                    __half2* dst =
                        (__half2*)((__half*)Cv + (size_t)m0 * Nout + n0);
                    *dst = __floats2half2_rn(v.x, v.y);
                } else {
                    float2* dst = (float2*)((float*)Cv + (size_t)m0 * Nout + n0);
                    if (flags & FLAG_ADD) {
                        float2 old = *dst;
                        v.x += old.x;
                        v.y += old.y;
                    }
                    *dst = v;
                }
            }
        }
    }
}

// ---------------- flash attention (causal + ALiBi, fp32, half out) ----------
__global__ __launch_bounds__(128) void attn_kernel(
    const float* __restrict__ qkv, __half* __restrict__ out) {
    __shared__ float Qs[64][65];
    __shared__ float Ks[32][65];
    __shared__ float Vs[32][65];
    __shared__ float Ss[64][33];

    int qt = blockIdx.x;
    int bh = blockIdx.y;
    int b = bh / NH, h = bh % NH;
    int t = threadIdx.x;
    int q = t >> 1;
    int half = t & 1;
    int dstart = half * 32;
    int nq = qt * 64 + q;
    float slope = c_slopes[h];
    const float scale = 0.125f;

    for (int i = 0; i < 32; i++) {
        int idx = t + i * 128;
        int row = idx >> 6, d = idx & 63;
        Qs[row][d] =
            qkv[((size_t)(b * Nn + qt * 64 + row) * (3 * EMB)) + h * DH + d] *
            scale;
    }

    float m = -1e30f, l = 0.f;
    float acc[32];
#pragma unroll
    for (int d = 0; d < 32; d++) acc[d] = 0.f;

    int kt_end = 2 * qt + 1;
    for (int kt = 0; kt <= kt_end; kt++) {
        __syncthreads();
        for (int i = 0; i < 16; i++) {
            int idx = t + i * 128;
            int row = idx >> 6, d = idx & 63;
            size_t base =
                (size_t)(b * Nn + kt * 32 + row) * (3 * EMB) + h * DH + d;
            Ks[row][d] = qkv[base + EMB];
            Vs[row][d] = qkv[base + 2 * EMB];
        }
        __syncthreads();

        for (int jj = 0; jj < 16; jj++) {
            int j = half * 16 + jj;
            int nk = kt * 32 + j;
            float s;
            if (nk > nq) {
                s = -1e30f;
            } else {
                s = 0.f;
#pragma unroll
                for (int d = 0; d < 64; d++) s = fmaf(Qs[q][d], Ks[j][d], s);
                s += slope * (float)nk;
            }
            Ss[q][j] = s;
        }
        __syncthreads();

        float tmax = -1e30f;
#pragma unroll
        for (int j = 0; j < 32; j++) tmax = fmaxf(tmax, Ss[q][j]);
        float newm = fmaxf(m, tmax);
        float corr = expf(m - newm);
        m = newm;
        l *= corr;
#pragma unroll
        for (int d = 0; d < 32; d++) acc[d] *= corr;
        for (int j = 0; j < 32; j++) {
            float p = expf(Ss[q][j] - newm);
            l += p;
#pragma unroll
            for (int d = 0; d < 32; d++)
                acc[d] = fmaf(p, Vs[j][dstart + d], acc[d]);
        }
    }

    float invl = 1.0f / l;
    __half* op = out + (size_t)(b * Nn + nq) * EMB + h * DH + dstart;
#pragma unroll
    for (int d = 0; d < 32; d++) op[d] = __float2half_rn(acc[d] * invl);
}

// ---------------- host orchestration -----------------------------------------
extern "C" void kernel_launch(void* const* d_in, const int* in_sizes, int n_in,
                              void* d_out, int out_size) {
    const float* x = (const float*)d_in[0];
    const float* wqkv = (const float*)d_in[1];
    const float* bqkv = (const float*)d_in[2];
    const float* wo = (const float*)d_in[3];
    const float* bo = (const float*)d_in[4];
    const float* ln1s = (const float*)d_in[5];
    const float* ln1b = (const float*)d_in[6];
    const float* ln2s = (const float*)d_in[7];
    const float* ln2b = (const float*)d_in[8];
    const float* w1 = (const float*)d_in[9];
    const float* w2 = (const float*)d_in[10];
    const float* lnfs = (const float*)d_in[11];
    const float* lnfb = (const float*)d_in[12];
    float* out = (float*)d_out;

    float *p_h, *p_qkv;
    __half *p_y, *p_o, *p_mid, *p_wqkv, *p_wo, *p_w1, *p_w2;
    cudaGetSymbolAddress((void**)&p_h, g_h);
    cudaGetSymbolAddress((void**)&p_y, g_y);
    cudaGetSymbolAddress((void**)&p_qkv, g_qkv);
    cudaGetSymbolAddress((void**)&p_o, g_o);
    cudaGetSymbolAddress((void**)&p_mid, g_mid);
    cudaGetSymbolAddress((void**)&p_wqkv, g_wqkv);
    cudaGetSymbolAddress((void**)&p_wo, g_wo);
    cudaGetSymbolAddress((void**)&p_w1, g_w1);
    cudaGetSymbolAddress((void**)&p_w2, g_w2);

    cudaFuncSetAttribute(gemm_fp16, cudaFuncAttributeMaxDynamicSharedMemorySize,
                         GEMM_SMEM);

    copy_kernel<<<(TOK * EMB + 255) / 256, 256>>>(x);  // launch 0

    transpose_half_all<<<TALL, dim3(32, 8)>>>(wqkv, wo, w1, w2, p_wqkv, p_wo,
                                              p_w1, p_w2);  // launch 1

    for (int L = 0; L < DEPTH; L++) {
        ln_kernel<<<TOK, 256>>>(p_h, ln1s + L * EMB, ln1b + L * EMB, p_y, 1);
        {  // qkv = y @ Wqkv + b (fp32 out)
            dim3 grid(3 * EMB / 64, TOK / 128);
            gemm_fp16<<<grid, 128, GEMM_SMEM>>>(
                p_y, p_wqkv + (size_t)L * EMB * 3 * EMB, bqkv + L * 3 * EMB,
                p_qkv, EMB, 3 * EMB, FLAG_BIAS);
        }
        {
            dim3 grid(Nn / 64, Bb * NH);
            attn_kernel<<<grid, 128>>>(p_qkv, p_o);
        }
        {  // h += o @ Wo + bo  (launch 5 in layer 0 — profiled)
            dim3 grid(EMB / 64, TOK / 128);
            gemm_fp16<<<grid, 128, GEMM_SMEM>>>(
                p_o, p_wo + (size_t)L * EMB * EMB, bo + L * EMB, p_h, EMB, EMB,
                FLAG_BIAS | FLAG_ADD);
        }
        ln_kernel<<<TOK, 256>>>(p_h, ln2s + L * EMB, ln2b + L * EMB, p_y, 1);
        {  // mid = gelu(y @ W1) (half out)
            dim3 grid(FF / 64, TOK / 128);
            gemm_fp16<<<grid, 128, GEMM_SMEM>>>(p_y,
                                                p_w1 + (size_t)L * EMB * FF,
                                                nullptr, p_mid, EMB, FF,
                                                FLAG_GELU | FLAG_HALF);
        }
        {  // h += mid @ W2
            dim3 grid(EMB / 64, TOK / 128);
            gemm_fp16<<<grid, 128, GEMM_SMEM>>>(p_mid,
                                                p_w2 + (size_t)L * FF * EMB,
                                                nullptr, p_h, FF, EMB,
                                                FLAG_ADD);
        }
    }

    ln_kernel<<<TOK, 256>>>(p_h, lnfs, lnfb, out, 0);
}

// round 10
// speedup vs baseline: 4.8407x; 4.8407x over previous
#include <cuda_runtime.h>
#include <cuda_fp16.h>
#include <math.h>
#include <stdint.h>

#define Bb 2
#define Nn 2048
#define EMB 768
#define NH 12
#define DH 64
#define DEPTH 6
#define FF 3072
#define TOK (Bb * Nn)  // 4096
#define QKVW (3 * EMB) // 2304
#define LN_EPS 1e-6f

// ---------------- scratch (static device globals) ---------------------------
__device__ float g_h[TOK * EMB];          // residual stream (fp32)
__device__ __half g_y[TOK * EMB];         // LN output (fp16)
__device__ __half g_qkv[TOK * 3 * EMB];   // qkv (fp16)
__device__ __half g_o[TOK * EMB];         // attention output (fp16)
__device__ __half g_mid[TOK * FF];        // FFN hidden (fp16)
// transposed fp16 weights ([Nout][K], K-major rows)
__device__ __half g_wqkv[DEPTH * EMB * 3 * EMB];
__device__ __half g_wo[DEPTH * EMB * EMB];
__device__ __half g_w1[DEPTH * EMB * FF];
__device__ __half g_w2[DEPTH * FF * EMB];

__constant__ float c_slopes[NH] = {
    0.5f, 0.25f, 0.125f, 0.0625f, 0.03125f, 0.015625f, 0.0078125f, 0.00390625f,
    0.70710678118654752f, 0.35355339059327376f, 0.17677669529663688f,
    0.08838834764831844f};

__device__ __forceinline__ void cp16(uint32_t dst, const void* src) {
    asm volatile("cp.async.ca.shared.global [%0], [%1], 16;" ::"r"(dst),
                 "l"(src));
}

__device__ __forceinline__ uint32_t packh2(float a, float b) {
    __half2 h = __floats2half2_rn(a, b);
    return *(uint32_t*)&h;
}

#define MMA_FP16(d, a, b)                                                     \
    asm volatile(                                                             \
        "mma.sync.aligned.m16n8k16.row.col.f32.f16.f16.f32 "                  \
        "{%0,%1,%2,%3},{%4,%5,%6,%7},{%8,%9},{%0,%1,%2,%3};"                  \
        : "+f"(d[0]), "+f"(d[1]), "+f"(d[2]), "+f"(d[3])                      \
        : "r"(a[0]), "r"(a[1]), "r"(a[2]), "r"(a[3]), "r"(b[0]), "r"(b[1]))

#define LDSM_X4(r0, r1, r2, r3, addr)                                        \
    asm volatile(                                                            \
        "ldmatrix.sync.aligned.m8n8.x4.shared.b16 {%0,%1,%2,%3}, [%4];"      \
        : "=r"(r0), "=r"(r1), "=r"(r2), "=r"(r3)                             \
        : "r"(addr))

#define LDSM_X4_T(r0, r1, r2, r3, addr)                                      \
    asm volatile(                                                            \
        "ldmatrix.sync.aligned.m8n8.x4.trans.shared.b16 {%0,%1,%2,%3}, "     \
        "[%4];"                                                              \
        : "=r"(r0), "=r"(r1), "=r"(r2), "=r"(r3)                             \
        : "r"(addr))

// ---------------- copy x -> h ------------------------------------------------
__global__ void copy_kernel(const float* __restrict__ x) {
    int i = blockIdx.x * blockDim.x + threadIdx.x;
    if (i < TOK * EMB) g_h[i] = x[i];
}

// ---------------- fused transpose + fp16 convert of ALL weights -------------
#define TQKV (72 * 24 * DEPTH)
#define TWO (24 * 24 * DEPTH)
#define TW1 (96 * 24 * DEPTH)
#define TW2 (24 * 96 * DEPTH)
#define TALL (TQKV + TWO + TW1 + TW2)

__global__ void transpose_half_all(const float* __restrict__ wqkv,
                                   const float* __restrict__ wo,
                                   const float* __restrict__ w1,
                                   const float* __restrict__ w2,
                                   __half* __restrict__ pwqkv,
                                   __half* __restrict__ pwo,
                                   __half* __restrict__ pw1,
                                   __half* __restrict__ pw2) {
    __shared__ float tile[32][33];
    int b = blockIdx.x;
    const float* W;
    __half* Wt;
    int K, N;
    if (b < TQKV) {
        W = wqkv; Wt = pwqkv; K = EMB; N = 3 * EMB;
    } else if (b < TQKV + TWO) {
        b -= TQKV; W = wo; Wt = pwo; K = EMB; N = EMB;
    } else if (b < TQKV + TWO + TW1) {
        b -= TQKV + TWO; W = w1; Wt = pw1; K = EMB; N = FF;
    } else {
        b -= TQKV + TWO + TW1; W = w2; Wt = pw2; K = FF; N = EMB;
    }
    int ntiles = N / 32, tpl = ntiles * (K / 32);
    int layer = b / tpl, rem = b % tpl;
    int bn = (rem % ntiles) * 32, bk = (rem / ntiles) * 32;
    W += (size_t)layer * K * N;
    Wt += (size_t)layer * K * N;
    int tx = threadIdx.x, ty = threadIdx.y;
#pragma unroll
    for (int i = 0; i < 32; i += 8)
        tile[ty + i][tx] = W[(size_t)(bk + ty + i) * N + bn + tx];
    __syncthreads();
#pragma unroll
    for (int i = 0; i < 32; i += 8)
        Wt[(size_t)(bn + ty + i) * K + bk + tx] =
            __float2half_rn(tile[tx][ty + i]);
}

// ---------------- LayerNorm (float in; float or half out) -------------------
__global__ void ln_kernel(const float* __restrict__ in,
                          const float* __restrict__ scale,
                          const float* __restrict__ bias, void* __restrict__ o,
                          int half_out) {
    int row = blockIdx.x;
    const float* p = in + (size_t)row * EMB;
    float s = 0.f, ss = 0.f;
    for (int i = threadIdx.x; i < EMB; i += 256) {
        float v = p[i];
        s += v;
        ss += v * v;
    }
#pragma unroll
    for (int of = 16; of; of >>= 1) {
        s += __shfl_xor_sync(0xffffffffu, s, of);
        ss += __shfl_xor_sync(0xffffffffu, ss, of);
    }
    __shared__ float sh_s[8], sh_ss[8];
    int w = threadIdx.x >> 5, lane = threadIdx.x & 31;
    if (lane == 0) { sh_s[w] = s; sh_ss[w] = ss; }
    __syncthreads();
    if (threadIdx.x < 32) {
        s = (lane < 8) ? sh_s[lane] : 0.f;
        ss = (lane < 8) ? sh_ss[lane] : 0.f;
#pragma unroll
        for (int of = 4; of; of >>= 1) {
            s += __shfl_xor_sync(0xffffffffu, s, of);
            ss += __shfl_xor_sync(0xffffffffu, ss, of);
        }
        if (lane == 0) { sh_s[0] = s; sh_ss[0] = ss; }
    }
    __syncthreads();
    float mean = sh_s[0] * (1.0f / EMB);
    float var = sh_ss[0] * (1.0f / EMB) - mean * mean;
    float inv = rsqrtf(var + LN_EPS);
    if (half_out) {
        __half* q = (__half*)o + (size_t)row * EMB;
        for (int i = threadIdx.x; i < EMB; i += 256)
            q[i] = __float2half_rn((p[i] - mean) * inv * scale[i] + bias[i]);
    } else {
        float* q = (float*)o + (size_t)row * EMB;
        for (int i = threadIdx.x; i < EMB; i += 256)
            q[i] = (p[i] - mean) * inv * scale[i] + bias[i];
    }
}

// ---------------- fp16 mma.sync GEMM: CTA 128x64, 4 warps, 4 CTA/SM ---------
#define FLAG_BIAS 1
#define FLAG_GELU 2
#define FLAG_ADD 4
#define FLAG_HALF 8

#define STAGES 4
#define A_STAGE 8192
#define B_STAGE 4096
#define STAGE_BYTES (A_STAGE + B_STAGE)
#define GEMM_SMEM (STAGES * STAGE_BYTES)

__device__ __forceinline__ float gelu_tanh(float x) {
    const float k0 = 0.7978845608028654f;
    return 0.5f * x * (1.0f + tanhf(k0 * (x + 0.044715f * x * x * x)));
}

__global__ __launch_bounds__(128, 4) void gemm_fp16(
    const __half* __restrict__ A, const __half* __restrict__ Wt,
    const float* __restrict__ bias, void* __restrict__ Cv, int K, int Nout,
    int flags) {
    extern __shared__ char smem[];
    const uint32_t sb = (uint32_t)__cvta_generic_to_shared(smem);
    const int tid = threadIdx.x;
    const int warp = tid >> 5, lane = tid & 31;
    const int wm = warp >> 1, wn = warp & 1;
    const int bm = blockIdx.y * 128, bn = blockIdx.x * 64;

    const __half* gA = A + (size_t)(bm + tid) * K;
    const int brow = tid >> 1, bc0 = (tid & 1) * 2;
    const __half* gB = Wt + (size_t)(bn + brow) * K + bc0 * 8;
    uint32_t stA[4], stB[2];
#pragma unroll
    for (int c = 0; c < 4; c++)
        stA[c] = sb + (uint32_t)tid * 64 +
                 (((uint32_t)(c ^ ((tid >> 1) & 3))) << 4);
#pragma unroll
    for (int i = 0; i < 2; i++)
        stB[i] = sb + A_STAGE + (uint32_t)brow * 64 +
                 (((uint32_t)((bc0 + i) ^ ((brow >> 1) & 3))) << 4);

#define LOAD_STAGE(s, t_)                                                  \
    do {                                                                   \
        const __half* _a = gA + (t_) * 32;                                 \
        const __half* _b = gB + (t_) * 32;                                 \
        uint32_t _so = (uint32_t)(s)*STAGE_BYTES;                          \
        _Pragma("unroll") for (int _c = 0; _c < 4; _c++)                   \
            cp16(stA[_c] + _so, _a + _c * 8);                              \
        _Pragma("unroll") for (int _i = 0; _i < 2; _i++)                   \
            cp16(stB[_i] + _so, _b + _i * 8);                              \
        asm volatile("cp.async.commit_group;");                            \
    } while (0)

    int arow7 = lane & 7;
    int a8 = ((lane >> 3) & 1) * 8;
    int acbit = lane >> 4;
    int axor = (arow7 >> 1) & 3;
    uint32_t aBase[4];
#pragma unroll
    for (int mf = 0; mf < 4; mf++) {
        int r = wm * 64 + mf * 16 + arow7 + a8;
        aBase[mf] = sb + (uint32_t)r * 64;
    }
    uint32_t aoff[2];
#pragma unroll
    for (int ks = 0; ks < 2; ks++)
        aoff[ks] = ((uint32_t)((2 * ks + acbit) ^ axor)) << 4;

    int brow7 = lane & 7;
    int bn8 = (lane >> 4) * 8;
    int bcb = (lane >> 3) & 1;
    int bxor = (brow7 >> 1) & 3;
    uint32_t bBase[2];
#pragma unroll
    for (int p = 0; p < 2; p++) {
        int r = wn * 32 + p * 16 + brow7 + bn8;
        bBase[p] = sb + A_STAGE + (uint32_t)r * 64;
    }
    uint32_t boff[2];
#pragma unroll
    for (int ks = 0; ks < 2; ks++)
        boff[ks] = ((uint32_t)((2 * ks + bcb) ^ bxor)) << 4;

    float acc[4][4][4];
#pragma unroll
    for (int i = 0; i < 4; i++)
#pragma unroll
        for (int j = 0; j < 4; j++)
#pragma unroll
            for (int c = 0; c < 4; c++) acc[i][j][c] = 0.f;

    const int T = K / 32;

    LOAD_STAGE(0, 0);
    LOAD_STAGE(1, 1);
    LOAD_STAGE(2, 2);

    for (int t = 0; t < T; t++) {
        int rem = ((t + 2 < T) ? (t + 2) : (T - 1)) - t;
        if (rem == 2)
            asm volatile("cp.async.wait_group 2;");
        else if (rem == 1)
            asm volatile("cp.async.wait_group 1;");
        else
            asm volatile("cp.async.wait_group 0;");
        __syncthreads();
        if (t + 3 < T) LOAD_STAGE((t + 3) & 3, t + 3);

        uint32_t so = (uint32_t)(t & 3) * STAGE_BYTES;
#pragma unroll
        for (int ks = 0; ks < 2; ks++) {
            uint32_t af[4][4], bf[4][2];
#pragma unroll
            for (int mf = 0; mf < 4; mf++)
                LDSM_X4(af[mf][0], af[mf][1], af[mf][2], af[mf][3],
                        aBase[mf] + so + aoff[ks]);
#pragma unroll
            for (int p = 0; p < 2; p++)
                LDSM_X4(bf[2 * p][0], bf[2 * p][1], bf[2 * p + 1][0],
                        bf[2 * p + 1][1], bBase[p] + so + boff[ks]);
#pragma unroll
            for (int mf = 0; mf < 4; mf++)
#pragma unroll
                for (int nf = 0; nf < 4; nf++)
                    MMA_FP16(acc[mf][nf], af[mf], bf[nf]);
        }
    }

    int r = lane >> 2, kq = lane & 3;
#pragma unroll
    for (int mf = 0; mf < 4; mf++) {
#pragma unroll
        for (int nf = 0; nf < 4; nf++) {
            int n0 = bn + wn * 32 + nf * 8 + kq * 2;
#pragma unroll
            for (int half = 0; half < 2; half++) {
                int m0 = bm + wm * 64 + mf * 16 + r + half * 8;
                float2 v;
                v.x = acc[mf][nf][half * 2 + 0];
                v.y = acc[mf][nf][half * 2 + 1];
                if (flags & FLAG_BIAS) {
                    v.x += bias[n0];
                    v.y += bias[n0 + 1];
                }
                if (flags & FLAG_GELU) {
                    v.x = gelu_tanh(v.x);
                    v.y = gelu_tanh(v.y);
                }
                if (flags & FLAG_HALF) {
                    __half2* dst =
                        (__half2*)((__half*)Cv + (size_t)m0 * Nout + n0);
                    *dst = __floats2half2_rn(v.x, v.y);
                } else {
                    float2* dst =
                        (float2*)((float*)Cv + (size_t)m0 * Nout + n0);
                    if (flags & FLAG_ADD) {
                        float2 old = *dst;
                        v.x += old.x;
                        v.y += old.y;
                    }
                    *dst = v;
                }
            }
        }
    }
}

// ---------------- flash attention w/ tensor cores (causal + ALiBi) ----------
// block: 128 thr = 4 warps, q-tile 64 (16 rows/warp), k-tile 64, fp16 mma.
// smem: Q 8KB | K/V double-buffered 2 x (8KB + 8KB) = 40KB total.
__global__ __launch_bounds__(128) void attn_mma(const __half* __restrict__ qkv,
                                                __half* __restrict__ out) {
    __shared__ __align__(16) char smem[40960];
    const uint32_t sb = (uint32_t)__cvta_generic_to_shared(smem);
    const int tid = threadIdx.x;
    const int w = tid >> 5, lane = tid & 31;
    const int qt = blockIdx.x, bh = blockIdx.y;
    const int b = bh / NH, h = bh % NH;
    const float slope = c_slopes[h];

    const int srow = tid >> 1, c0 = (tid & 1) * 4;
    const int sxor = srow & 7;
    const uint32_t rowoff = sb + (uint32_t)srow * 128;

    // --- load Q tile (group 0) ---
    {
        const __half* gQ = qkv +
                           (size_t)(b * Nn + qt * 64 + srow) * QKVW + h * DH +
                           c0 * 8;
#pragma unroll
        for (int i = 0; i < 4; i++)
            cp16(rowoff + (((uint32_t)((c0 + i) ^ sxor)) << 4), gQ + i * 8);
        asm volatile("cp.async.commit_group;");
    }

#define LOAD_KV(kt_, buf_)                                                   \
    do {                                                                     \
        const __half* _gK = qkv +                                            \
                            (size_t)(b * Nn + (kt_)*64 + srow) * QKVW + EMB + \
                            h * DH + c0 * 8;                                 \
        uint32_t _base = rowoff + 8192 + (uint32_t)(buf_)*16384;             \
        _Pragma("unroll") for (int _i = 0; _i < 4; _i++)                     \
            cp16(_base + (((uint32_t)((c0 + _i) ^ sxor)) << 4), _gK + _i * 8); \
        _Pragma("unroll") for (int _i = 0; _i < 4; _i++)                     \
            cp16(_base + 8192 + (((uint32_t)((c0 + _i) ^ sxor)) << 4),       \
                 _gK + EMB + _i * 8);                                        \
        asm volatile("cp.async.commit_group;");                              \
    } while (0)

    LOAD_KV(0, 0);

    // --- preload Q fragments (after Q group done) ---
    asm volatile("cp.async.wait_group 1;");
    __syncthreads();
    const int arow7 = lane & 7;
    const int a8 = ((lane >> 3) & 1) * 8;
    const int acbit = lane >> 4;
    uint32_t Qf[4][4];
    {
        uint32_t qrow = (uint32_t)(w * 16 + arow7 + a8);
        uint32_t qaddr = sb + qrow * 128;
#pragma unroll
        for (int kc = 0; kc < 4; kc++)
            LDSM_X4(Qf[kc][0], Qf[kc][1], Qf[kc][2], Qf[kc][3],
                    qaddr + (((uint32_t)((2 * kc + acbit) ^ arow7)) << 4));
    }

    const int r = lane >> 2, kq = lane & 3;
    const int row0 = qt * 64 + w * 16 + r;
    const int row1 = row0 + 8;
    float m0 = -1e30f, m1 = -1e30f, l0 = 0.f, l1 = 0.f;
    float O[8][4];
#pragma unroll
    for (int dt = 0; dt < 8; dt++)
#pragma unroll
        for (int c = 0; c < 4; c++) O[dt][c] = 0.f;

    // B-frag (K) addressing
    const int bg = lane >> 3;
    const int bcb = bg & 1;
    const int brofs = (bg >> 1) * 8;
    const int brow7 = lane & 7;
    // V trans addressing
    const uint32_t vrowlocal = (uint32_t)((lane & 7) + ((lane >> 3) & 1) * 8);
    const int vcbit = lane >> 4;

    for (int kt = 0; kt <= qt; kt++) {
        int buf = kt & 1;
        if (kt < qt) LOAD_KV(kt + 1, buf ^ 1);
        if (kt < qt)
            asm volatile("cp.async.wait_group 1;");
        else
            asm volatile("cp.async.wait_group 0;");
        __syncthreads();

        uint32_t kbase = sb + 8192 + (uint32_t)buf * 16384;
        uint32_t vbase = kbase + 8192;

        // ---- S = Q @ K^T ----
        float S[8][4];
#pragma unroll
        for (int nt = 0; nt < 8; nt++)
#pragma unroll
            for (int c = 0; c < 4; c++) S[nt][c] = 0.f;
#pragma unroll
        for (int kc = 0; kc < 4; kc++) {
            uint32_t bf[8][2];
#pragma unroll
            for (int p = 0; p < 4; p++) {
                uint32_t rr = (uint32_t)(p * 16 + brofs + brow7);
                LDSM_X4(bf[2 * p][0], bf[2 * p][1], bf[2 * p + 1][0],
                        bf[2 * p + 1][1],
                        kbase + rr * 128 +
                            (((uint32_t)((2 * kc + bcb) ^ brow7)) << 4));
            }
#pragma unroll
            for (int nt = 0; nt < 8; nt++) MMA_FP16(S[nt], Qf[kc], bf[nt]);
        }

        // ---- scale + alibi + causal mask ----
        bool diag = (kt == qt);
        float mx0 = -1e30f, mx1 = -1e30f;
#pragma unroll
        for (int nt = 0; nt < 8; nt++) {
            int colb = kt * 64 + nt * 8 + kq * 2;
#pragma unroll
            for (int c = 0; c < 4; c++) {
                int col = colb + (c & 1);
                float v = S[nt][c] * 0.125f + slope * (float)col;
                if (diag && col > ((c < 2) ? row0 : row1)) v = -1e30f;
                S[nt][c] = v;
                if (c < 2)
                    mx0 = fmaxf(mx0, v);
                else
                    mx1 = fmaxf(mx1, v);
            }
        }
        mx0 = fmaxf(mx0, __shfl_xor_sync(0xffffffffu, mx0, 1));
        mx0 = fmaxf(mx0, __shfl_xor_sync(0xffffffffu, mx0, 2));
        mx1 = fmaxf(mx1, __shfl_xor_sync(0xffffffffu, mx1, 1));
        mx1 = fmaxf(mx1, __shfl_xor_sync(0xffffffffu, mx1, 2));

        float nm0 = fmaxf(m0, mx0), nm1 = fmaxf(m1, mx1);
        float corr0 = __expf(m0 - nm0), corr1 = __expf(m1 - nm1);
        m0 = nm0;
        m1 = nm1;

        float sum0 = 0.f, sum1 = 0.f;
#pragma unroll
        for (int nt = 0; nt < 8; nt++) {
            float p0 = __expf(S[nt][0] - m0);
            float p1 = __expf(S[nt][1] - m0);
            float p2 = __expf(S[nt][2] - m1);
            float p3 = __expf(S[nt][3] - m1);
            S[nt][0] = p0;
            S[nt][1] = p1;
            S[nt][2] = p2;
            S[nt][3] = p3;
            sum0 += p0 + p1;
            sum1 += p2 + p3;
        }
        sum0 += __shfl_xor_sync(0xffffffffu, sum0, 1);
        sum0 += __shfl_xor_sync(0xffffffffu, sum0, 2);
        sum1 += __shfl_xor_sync(0xffffffffu, sum1, 1);
        sum1 += __shfl_xor_sync(0xffffffffu, sum1, 2);
        l0 = l0 * corr0 + sum0;
        l1 = l1 * corr1 + sum1;

#pragma unroll
        for (int dt = 0; dt < 8; dt++) {
            O[dt][0] *= corr0;
            O[dt][1] *= corr0;
            O[dt][2] *= corr1;
            O[dt][3] *= corr1;
        }

        // ---- O += P @ V ----
#pragma unroll
        for (int kc2 = 0; kc2 < 4; kc2++) {
            uint32_t aP[4];
            aP[0] = packh2(S[2 * kc2][0], S[2 * kc2][1]);
            aP[1] = packh2(S[2 * kc2][2], S[2 * kc2][3]);
            aP[2] = packh2(S[2 * kc2 + 1][0], S[2 * kc2 + 1][1]);
            aP[3] = packh2(S[2 * kc2 + 1][2], S[2 * kc2 + 1][3]);
            uint32_t vrow = (uint32_t)(kc2 * 16) + vrowlocal;
            uint32_t vra = vbase + vrow * 128;
            uint32_t vswz = vrow & 7;
#pragma unroll
            for (int cc = 0; cc < 4; cc++) {
                uint32_t v0, v1, v2, v3;
                LDSM_X4_T(v0, v1, v2, v3,
                          vra + (((uint32_t)((2 * cc + vcbit) ^ vswz)) << 4));
                uint32_t bA[2] = {v0, v1}, bB[2] = {v2, v3};
                MMA_FP16(O[2 * cc], aP, bA);
                MMA_FP16(O[2 * cc + 1], aP, bB);
            }
        }
        __syncthreads();
    }

    // ---- finalize + write fp16 ----
    float i0 = 1.0f / l0, i1 = 1.0f / l1;
    __half* o0 = out + (size_t)(b * Nn + row0) * EMB + h * DH + kq * 2;
    __half* o1 = out + (size_t)(b * Nn + row1) * EMB + h * DH + kq * 2;
#pragma unroll
    for (int dt = 0; dt < 8; dt++) {
        *(__half2*)(o0 + dt * 8) = __floats2half2_rn(O[dt][0] * i0, O[dt][1] * i0);
        *(__half2*)(o1 + dt * 8) = __floats2half2_rn(O[dt][2] * i1, O[dt][3] * i1);
    }
}

// ---------------- host orchestration -----------------------------------------
extern "C" void kernel_launch(void* const* d_in, const int* in_sizes, int n_in,
                              void* d_out, int out_size) {
    const float* x = (const float*)d_in[0];
    const float* wqkv = (const float*)d_in[1];
    const float* bqkv = (const float*)d_in[2];
    const float* wo = (const float*)d_in[3];
    const float* bo = (const float*)d_in[4];
    const float* ln1s = (const float*)d_in[5];
    const float* ln1b = (const float*)d_in[6];
    const float* ln2s = (const float*)d_in[7];
    const float* ln2b = (const float*)d_in[8];
    const float* w1 = (const float*)d_in[9];
    const float* w2 = (const float*)d_in[10];
    const float* lnfs = (const float*)d_in[11];
    const float* lnfb = (const float*)d_in[12];
    float* out = (float*)d_out;

    float* p_h;
    __half *p_y, *p_qkv, *p_o, *p_mid, *p_wqkv, *p_wo, *p_w1, *p_w2;
    cudaGetSymbolAddress((void**)&p_h, g_h);
    cudaGetSymbolAddress((void**)&p_y, g_y);
    cudaGetSymbolAddress((void**)&p_qkv, g_qkv);
    cudaGetSymbolAddress((void**)&p_o, g_o);
    cudaGetSymbolAddress((void**)&p_mid, g_mid);
    cudaGetSymbolAddress((void**)&p_wqkv, g_wqkv);
    cudaGetSymbolAddress((void**)&p_wo, g_wo);
    cudaGetSymbolAddress((void**)&p_w1, g_w1);
    cudaGetSymbolAddress((void**)&p_w2, g_w2);

    cudaFuncSetAttribute(gemm_fp16, cudaFuncAttributeMaxDynamicSharedMemorySize,
                         GEMM_SMEM);

    copy_kernel<<<(TOK * EMB + 255) / 256, 256>>>(x);

    transpose_half_all<<<TALL, dim3(32, 8)>>>(wqkv, wo, w1, w2, p_wqkv, p_wo,
                                              p_w1, p_w2);

    for (int L = 0; L < DEPTH; L++) {
        ln_kernel<<<TOK, 256>>>(p_h, ln1s + L * EMB, ln1b + L * EMB, p_y, 1);
        {  // qkv = y @ Wqkv + b (fp16 out)
            dim3 grid(3 * EMB / 64, TOK / 128);
            gemm_fp16<<<grid, 128, GEMM_SMEM>>>(
                p_y, p_wqkv + (size_t)L * EMB * 3 * EMB, bqkv + L * 3 * EMB,
                p_qkv, EMB, 3 * EMB, FLAG_BIAS | FLAG_HALF);
        }
        {  // flash attention (tensor cores)
            dim3 grid(Nn / 64, Bb * NH);
            attn_mma<<<grid, 128>>>(p_qkv, p_o);
        }
        {  // h += o @ Wo + bo
            dim3 grid(EMB / 64, TOK / 128);
            gemm_fp16<<<grid, 128, GEMM_SMEM>>>(
                p_o, p_wo + (size_t)L * EMB * EMB, bo + L * EMB, p_h, EMB, EMB,
                FLAG_BIAS | FLAG_ADD);
        }
        ln_kernel<<<TOK, 256>>>(p_h, ln2s + L * EMB, ln2b + L * EMB, p_y, 1);
        {  // mid = gelu(y @ W1) (half out)
            dim3 grid(FF / 64, TOK / 128);
            gemm_fp16<<<grid, 128, GEMM_SMEM>>>(p_y,
                                                p_w1 + (size_t)L * EMB * FF,
                                                nullptr, p_mid, EMB, FF,
                                                FLAG_GELU | FLAG_HALF);
        }
        {  // h += mid @ W2
            dim3 grid(EMB / 64, TOK / 128);
            gemm_fp16<<<grid, 128, GEMM_SMEM>>>(p_mid,
                                                p_w2 + (size_t)L * FF * EMB,
                                                nullptr, p_h, FF, EMB,
                                                FLAG_ADD);
        }
    }

    ln_kernel<<<TOK, 256>>>(p_h, lnfs, lnfb, out, 0);
}

// round 11
// speedup vs baseline: 5.4563x; 1.1272x over previous
#include <cuda_runtime.h>
#include <cuda_fp16.h>
#include <math.h>
#include <stdint.h>

#define Bb 2
#define Nn 2048
#define EMB 768
#define NH 12
#define DH 64
#define DEPTH 6
#define FF 3072
#define TOK (Bb * Nn)  // 4096
#define QKVW (3 * EMB) // 2304
#define LN_EPS 1e-6f

// ---------------- scratch (static device globals) ---------------------------
__device__ float g_h[TOK * EMB];
__device__ __half g_y[TOK * EMB];
__device__ __half g_qkv[TOK * 3 * EMB];
__device__ __half g_o[TOK * EMB];
__device__ __half g_mid[TOK * FF];
__device__ __half g_wqkv[DEPTH * EMB * 3 * EMB];
__device__ __half g_wo[DEPTH * EMB * EMB];
__device__ __half g_w1[DEPTH * EMB * FF];
__device__ __half g_w2[DEPTH * FF * EMB];

__constant__ float c_slopes[NH] = {
    0.5f, 0.25f, 0.125f, 0.0625f, 0.03125f, 0.015625f, 0.0078125f, 0.00390625f,
    0.70710678118654752f, 0.35355339059327376f, 0.17677669529663688f,
    0.08838834764831844f};

__device__ __forceinline__ void cp16(uint32_t dst, const void* src) {
    asm volatile("cp.async.cg.shared.global [%0], [%1], 16;" ::"r"(dst),
                 "l"(src));
}

__device__ __forceinline__ uint32_t packh2(float a, float b) {
    __half2 h = __floats2half2_rn(a, b);
    return *(uint32_t*)&h;
}

#define MMA_FP16(d, a, b)                                                     \
    asm volatile(                                                             \
        "mma.sync.aligned.m16n8k16.row.col.f32.f16.f16.f32 "                  \
        "{%0,%1,%2,%3},{%4,%5,%6,%7},{%8,%9},{%0,%1,%2,%3};"                  \
        : "+f"(d[0]), "+f"(d[1]), "+f"(d[2]), "+f"(d[3])                      \
        : "r"(a[0]), "r"(a[1]), "r"(a[2]), "r"(a[3]), "r"(b[0]), "r"(b[1]))

#define LDSM_X4(r0, r1, r2, r3, addr)                                        \
    asm volatile(                                                            \
        "ldmatrix.sync.aligned.m8n8.x4.shared.b16 {%0,%1,%2,%3}, [%4];"      \
        : "=r"(r0), "=r"(r1), "=r"(r2), "=r"(r3)                             \
        : "r"(addr))

#define LDSM_X4_T(r0, r1, r2, r3, addr)                                      \
    asm volatile(                                                            \
        "ldmatrix.sync.aligned.m8n8.x4.trans.shared.b16 {%0,%1,%2,%3}, "     \
        "[%4];"                                                              \
        : "=r"(r0), "=r"(r1), "=r"(r2), "=r"(r3)                             \
        : "r"(addr))

// ---------------- copy x -> h ------------------------------------------------
__global__ void copy_kernel(const float* __restrict__ x) {
    int i = blockIdx.x * blockDim.x + threadIdx.x;
    if (i < TOK * EMB) g_h[i] = x[i];
}

// ---------------- fused transpose + fp16 convert of ALL weights -------------
#define TQKV (72 * 24 * DEPTH)
#define TWO (24 * 24 * DEPTH)
#define TW1 (96 * 24 * DEPTH)
#define TW2 (24 * 96 * DEPTH)
#define TALL (TQKV + TWO + TW1 + TW2)

__global__ void transpose_half_all(const float* __restrict__ wqkv,
                                   const float* __restrict__ wo,
                                   const float* __restrict__ w1,
                                   const float* __restrict__ w2,
                                   __half* __restrict__ pwqkv,
                                   __half* __restrict__ pwo,
                                   __half* __restrict__ pw1,
                                   __half* __restrict__ pw2) {
    __shared__ float tile[32][33];
    int b = blockIdx.x;
    const float* W;
    __half* Wt;
    int K, N;
    if (b < TQKV) {
        W = wqkv; Wt = pwqkv; K = EMB; N = 3 * EMB;
    } else if (b < TQKV + TWO) {
        b -= TQKV; W = wo; Wt = pwo; K = EMB; N = EMB;
    } else if (b < TQKV + TWO + TW1) {
        b -= TQKV + TWO; W = w1; Wt = pw1; K = EMB; N = FF;
    } else {
        b -= TQKV + TWO + TW1; W = w2; Wt = pw2; K = FF; N = EMB;
    }
    int ntiles = N / 32, tpl = ntiles * (K / 32);
    int layer = b / tpl, rem = b % tpl;
    int bn = (rem % ntiles) * 32, bk = (rem / ntiles) * 32;
    W += (size_t)layer * K * N;
    Wt += (size_t)layer * K * N;
    int tx = threadIdx.x, ty = threadIdx.y;
#pragma unroll
    for (int i = 0; i < 32; i += 8)
        tile[ty + i][tx] = W[(size_t)(bk + ty + i) * N + bn + tx];
    __syncthreads();
#pragma unroll
    for (int i = 0; i < 32; i += 8)
        Wt[(size_t)(bn + ty + i) * K + bk + tx] =
            __float2half_rn(tile[tx][ty + i]);
}

// ---------------- LayerNorm (float in; float or half out) -------------------
__global__ void ln_kernel(const float* __restrict__ in,
                          const float* __restrict__ scale,
                          const float* __restrict__ bias, void* __restrict__ o,
                          int half_out) {
    int row = blockIdx.x;
    const float* p = in + (size_t)row * EMB;
    float s = 0.f, ss = 0.f;
    for (int i = threadIdx.x; i < EMB; i += 256) {
        float v = p[i];
        s += v;
        ss += v * v;
    }
#pragma unroll
    for (int of = 16; of; of >>= 1) {
        s += __shfl_xor_sync(0xffffffffu, s, of);
        ss += __shfl_xor_sync(0xffffffffu, ss, of);
    }
    __shared__ float sh_s[8], sh_ss[8];
    int w = threadIdx.x >> 5, lane = threadIdx.x & 31;
    if (lane == 0) { sh_s[w] = s; sh_ss[w] = ss; }
    __syncthreads();
    if (threadIdx.x < 32) {
        s = (lane < 8) ? sh_s[lane] : 0.f;
        ss = (lane < 8) ? sh_ss[lane] : 0.f;
#pragma unroll
        for (int of = 4; of; of >>= 1) {
            s += __shfl_xor_sync(0xffffffffu, s, of);
            ss += __shfl_xor_sync(0xffffffffu, ss, of);
        }
        if (lane == 0) { sh_s[0] = s; sh_ss[0] = ss; }
    }
    __syncthreads();
    float mean = sh_s[0] * (1.0f / EMB);
    float var = sh_ss[0] * (1.0f / EMB) - mean * mean;
    float inv = rsqrtf(var + LN_EPS);
    if (half_out) {
        __half* q = (__half*)o + (size_t)row * EMB;
        for (int i = threadIdx.x; i < EMB; i += 256)
            q[i] = __float2half_rn((p[i] - mean) * inv * scale[i] + bias[i]);
    } else {
        float* q = (float*)o + (size_t)row * EMB;
        for (int i = threadIdx.x; i < EMB; i += 256)
            q[i] = (p[i] - mean) * inv * scale[i] + bias[i];
    }
}

// ---------------- fp16 mma.sync GEMM, templated CTA N-tile ------------------
// C[M,Nout] = A[M,K] @ Wt[Nout,K]^T  (+bias, +gelu, +=C, half-out)
// BN=64 : 4 warps 2m x 2n, warp 64x32, 4 CTA/SM (48KB smem)
// BN=128: 4 warps 2m x 2n, warp 64x64, 2 CTA/SM (64KB smem)
#define FLAG_BIAS 1
#define FLAG_GELU 2
#define FLAG_ADD 4
#define FLAG_HALF 8

#define STAGES 4
#define A_STAGE 8192

__device__ __forceinline__ float gelu_tanh(float x) {
    const float k0 = 0.7978845608028654f;
    return 0.5f * x * (1.0f + tanhf(k0 * (x + 0.044715f * x * x * x)));
}

template <int BN>
__global__ __launch_bounds__(128, BN == 64 ? 4 : 2) void gemm_fp16(
    const __half* __restrict__ A, const __half* __restrict__ Wt,
    const float* __restrict__ bias, void* __restrict__ Cv, int K, int Nout,
    int flags) {
    constexpr int B_STAGE = BN * 64;  // BN rows x 64B
    constexpr int STAGE_BYTES = A_STAGE + B_STAGE;
    constexpr int NF = BN / 16;  // n-frags per warp (4 or 8)
    constexpr int NP = BN / 32;  // ldmatrix x4 pairs (2 or 4)

    extern __shared__ char smem[];
    const uint32_t sb = (uint32_t)__cvta_generic_to_shared(smem);
    const int tid = threadIdx.x;
    const int warp = tid >> 5, lane = tid & 31;
    const int wm = warp >> 1, wn = warp & 1;
    const int bm = blockIdx.y * 128, bn = blockIdx.x * BN;

    // ---- staging ----
    const __half* gA = A + (size_t)(bm + tid) * K;
    uint32_t stA[4];
#pragma unroll
    for (int c = 0; c < 4; c++)
        stA[c] = sb + (uint32_t)tid * 64 +
                 (((uint32_t)(c ^ ((tid >> 1) & 3))) << 4);

    const __half* gB;
    uint32_t stB[4];
    int nbcp;
    if (BN == 128) {
        gB = Wt + (size_t)(bn + tid) * K;
        nbcp = 4;
#pragma unroll
        for (int c = 0; c < 4; c++)
            stB[c] = sb + A_STAGE + (uint32_t)tid * 64 +
                     (((uint32_t)(c ^ ((tid >> 1) & 3))) << 4);
    } else {
        const int brow = tid >> 1, bc0 = (tid & 1) * 2;
        gB = Wt + (size_t)(bn + brow) * K + bc0 * 8;
        nbcp = 2;
#pragma unroll
        for (int i = 0; i < 2; i++)
            stB[i] = sb + A_STAGE + (uint32_t)brow * 64 +
                     (((uint32_t)((bc0 + i) ^ ((brow >> 1) & 3))) << 4);
    }

#define LOAD_STAGE(s, t_)                                                  \
    do {                                                                   \
        const __half* _a = gA + (t_) * 32;                                 \
        const __half* _b = gB + (t_) * 32;                                 \
        uint32_t _so = (uint32_t)(s)*STAGE_BYTES;                          \
        _Pragma("unroll") for (int _c = 0; _c < 4; _c++)                   \
            cp16(stA[_c] + _so, _a + _c * 8);                              \
        _Pragma("unroll") for (int _i = 0; _i < 4; _i++) if (_i < nbcp)    \
            cp16(stB[_i] + _so, _b + _i * 8);                              \
        asm volatile("cp.async.commit_group;");                            \
    } while (0)

    // ---- A fragment addressing (validated) ----
    int arow7 = lane & 7;
    int a8 = ((lane >> 3) & 1) * 8;
    int acbit = lane >> 4;
    int axor = (arow7 >> 1) & 3;
    uint32_t aBase[4];
#pragma unroll
    for (int mf = 0; mf < 4; mf++) {
        int r = wm * 64 + mf * 16 + arow7 + a8;
        aBase[mf] = sb + (uint32_t)r * 64;
    }
    uint32_t aoff[2];
#pragma unroll
    for (int ks = 0; ks < 2; ks++)
        aoff[ks] = ((uint32_t)((2 * ks + acbit) ^ axor)) << 4;

    // ---- B fragment addressing (x4 -> 2 n-frags) ----
    int brow7 = lane & 7;
    int bn8 = (lane >> 4) * 8;
    int bcb = (lane >> 3) & 1;
    int bxor = (brow7 >> 1) & 3;
    uint32_t bBase[NP];
#pragma unroll
    for (int p = 0; p < NP; p++) {
        int r = wn * (BN / 2) + p * 16 + brow7 + bn8;
        bBase[p] = sb + A_STAGE + (uint32_t)r * 64;
    }
    uint32_t boff[2];
#pragma unroll
    for (int ks = 0; ks < 2; ks++)
        boff[ks] = ((uint32_t)((2 * ks + bcb) ^ bxor)) << 4;

    float acc[4][NF][4];
#pragma unroll
    for (int i = 0; i < 4; i++)
#pragma unroll
        for (int j = 0; j < NF; j++)
#pragma unroll
            for (int c = 0; c < 4; c++) acc[i][j][c] = 0.f;

    const int T = K / 32;

    LOAD_STAGE(0, 0);
    LOAD_STAGE(1, 1);
    LOAD_STAGE(2, 2);

    for (int t = 0; t < T; t++) {
        int rem = ((t + 2 < T) ? (t + 2) : (T - 1)) - t;
        if (rem == 2)
            asm volatile("cp.async.wait_group 2;");
        else if (rem == 1)
            asm volatile("cp.async.wait_group 1;");
        else
            asm volatile("cp.async.wait_group 0;");
        __syncthreads();
        if (t + 3 < T) LOAD_STAGE((t + 3) & 3, t + 3);

        uint32_t so = (uint32_t)(t & 3) * STAGE_BYTES;
#pragma unroll
        for (int ks = 0; ks < 2; ks++) {
            uint32_t af[4][4];
#pragma unroll
            for (int mf = 0; mf < 4; mf++)
                LDSM_X4(af[mf][0], af[mf][1], af[mf][2], af[mf][3],
                        aBase[mf] + so + aoff[ks]);
#pragma unroll
            for (int p = 0; p < NP; p++) {
                uint32_t bf0[2], bf1[2];
                LDSM_X4(bf0[0], bf0[1], bf1[0], bf1[1],
                        bBase[p] + so + boff[ks]);
#pragma unroll
                for (int mf = 0; mf < 4; mf++) {
                    MMA_FP16(acc[mf][2 * p], af[mf], bf0);
                    MMA_FP16(acc[mf][2 * p + 1], af[mf], bf1);
                }
            }
        }
    }

    // ---- epilogue ----
    int r = lane >> 2, kq = lane & 3;
#pragma unroll
    for (int mf = 0; mf < 4; mf++) {
#pragma unroll
        for (int nf = 0; nf < NF; nf++) {
            int n0 = bn + wn * (BN / 2) + nf * 8 + kq * 2;
#pragma unroll
            for (int half = 0; half < 2; half++) {
                int m0 = bm + wm * 64 + mf * 16 + r + half * 8;
                float2 v;
                v.x = acc[mf][nf][half * 2 + 0];
                v.y = acc[mf][nf][half * 2 + 1];
                if (flags & FLAG_BIAS) {
                    v.x += bias[n0];
                    v.y += bias[n0 + 1];
                }
                if (flags & FLAG_GELU) {
                    v.x = gelu_tanh(v.x);
                    v.y = gelu_tanh(v.y);
                }
                if (flags & FLAG_HALF) {
                    __half2* dst =
                        (__half2*)((__half*)Cv + (size_t)m0 * Nout + n0);
                    *dst = __floats2half2_rn(v.x, v.y);
                } else {
                    float2* dst =
                        (float2*)((float*)Cv + (size_t)m0 * Nout + n0);
                    if (flags & FLAG_ADD) {
                        float2 old = *dst;
                        v.x += old.x;
                        v.y += old.y;
                    }
                    *dst = v;
                }
            }
        }
    }
}

#define GEMM_SMEM_64 (STAGES * (A_STAGE + 64 * 64))
#define GEMM_SMEM_128 (STAGES * (A_STAGE + 128 * 64))

// ---------------- flash attention w/ tensor cores (causal + ALiBi) ----------
__global__ __launch_bounds__(128) void attn_mma(const __half* __restrict__ qkv,
                                                __half* __restrict__ out) {
    __shared__ __align__(16) char smem[40960];
    const uint32_t sb = (uint32_t)__cvta_generic_to_shared(smem);
    const int tid = threadIdx.x;
    const int w = tid >> 5, lane = tid & 31;
    const int qt = blockIdx.x, bh = blockIdx.y;
    const int b = bh / NH, h = bh % NH;
    const float slope = c_slopes[h];

    const int srow = tid >> 1, c0 = (tid & 1) * 4;
    const int sxor = srow & 7;
    const uint32_t rowoff = sb + (uint32_t)srow * 128;

    {
        const __half* gQ = qkv +
                           (size_t)(b * Nn + qt * 64 + srow) * QKVW + h * DH +
                           c0 * 8;
#pragma unroll
        for (int i = 0; i < 4; i++)
            cp16(rowoff + (((uint32_t)((c0 + i) ^ sxor)) << 4), gQ + i * 8);
        asm volatile("cp.async.commit_group;");
    }

#define LOAD_KV(kt_, buf_)                                                   \
    do {                                                                     \
        const __half* _gK = qkv +                                            \
                            (size_t)(b * Nn + (kt_)*64 + srow) * QKVW + EMB + \
                            h * DH + c0 * 8;                                 \
        uint32_t _base = rowoff + 8192 + (uint32_t)(buf_)*16384;             \
        _Pragma("unroll") for (int _i = 0; _i < 4; _i++)                     \
            cp16(_base + (((uint32_t)((c0 + _i) ^ sxor)) << 4), _gK + _i * 8); \
        _Pragma("unroll") for (int _i = 0; _i < 4; _i++)                     \
            cp16(_base + 8192 + (((uint32_t)((c0 + _i) ^ sxor)) << 4),       \
                 _gK + EMB + _i * 8);                                        \
        asm volatile("cp.async.commit_group;");                              \
    } while (0)

    LOAD_KV(0, 0);

    asm volatile("cp.async.wait_group 1;");
    __syncthreads();
    const int arow7 = lane & 7;
    const int a8 = ((lane >> 3) & 1) * 8;
    const int acbit = lane >> 4;
    uint32_t Qf[4][4];
    {
        uint32_t qrow = (uint32_t)(w * 16 + arow7 + a8);
        uint32_t qaddr = sb + qrow * 128;
#pragma unroll
        for (int kc = 0; kc < 4; kc++)
            LDSM_X4(Qf[kc][0], Qf[kc][1], Qf[kc][2], Qf[kc][3],
                    qaddr + (((uint32_t)((2 * kc + acbit) ^ arow7)) << 4));
    }

    const int r = lane >> 2, kq = lane & 3;
    const int row0 = qt * 64 + w * 16 + r;
    const int row1 = row0 + 8;
    float m0 = -1e30f, m1 = -1e30f, l0 = 0.f, l1 = 0.f;
    float O[8][4];
#pragma unroll
    for (int dt = 0; dt < 8; dt++)
#pragma unroll
        for (int c = 0; c < 4; c++) O[dt][c] = 0.f;

    const int bg = lane >> 3;
    const int bcb = bg & 1;
    const int brofs = (bg >> 1) * 8;
    const int brow7 = lane & 7;
    const uint32_t vrowlocal = (uint32_t)((lane & 7) + ((lane >> 3) & 1) * 8);
    const int vcbit = lane >> 4;

    for (int kt = 0; kt <= qt; kt++) {
        int buf = kt & 1;
        if (kt < qt) LOAD_KV(kt + 1, buf ^ 1);
        if (kt < qt)
            asm volatile("cp.async.wait_group 1;");
        else
            asm volatile("cp.async.wait_group 0;");
        __syncthreads();

        uint32_t kbase = sb + 8192 + (uint32_t)buf * 16384;
        uint32_t vbase = kbase + 8192;

        float S[8][4];
#pragma unroll
        for (int nt = 0; nt < 8; nt++)
#pragma unroll
            for (int c = 0; c < 4; c++) S[nt][c] = 0.f;
#pragma unroll
        for (int kc = 0; kc < 4; kc++) {
            uint32_t bf[8][2];
#pragma unroll
            for (int p = 0; p < 4; p++) {
                uint32_t rr = (uint32_t)(p * 16 + brofs + brow7);
                LDSM_X4(bf[2 * p][0], bf[2 * p][1], bf[2 * p + 1][0],
                        bf[2 * p + 1][1],
                        kbase + rr * 128 +
                            (((uint32_t)((2 * kc + bcb) ^ brow7)) << 4));
            }
#pragma unroll
            for (int nt = 0; nt < 8; nt++) MMA_FP16(S[nt], Qf[kc], bf[nt]);
        }

        bool diag = (kt == qt);
        float mx0 = -1e30f, mx1 = -1e30f;
#pragma unroll
        for (int nt = 0; nt < 8; nt++) {
            int colb = kt * 64 + nt * 8 + kq * 2;
#pragma unroll
            for (int c = 0; c < 4; c++) {
                int col = colb + (c & 1);
                float v = S[nt][c] * 0.125f + slope * (float)col;
                if (diag && col > ((c < 2) ? row0 : row1)) v = -1e30f;
                S[nt][c] = v;
                if (c < 2)
                    mx0 = fmaxf(mx0, v);
                else
                    mx1 = fmaxf(mx1, v);
            }
        }
        mx0 = fmaxf(mx0, __shfl_xor_sync(0xffffffffu, mx0, 1));
        mx0 = fmaxf(mx0, __shfl_xor_sync(0xffffffffu, mx0, 2));
        mx1 = fmaxf(mx1, __shfl_xor_sync(0xffffffffu, mx1, 1));
        mx1 = fmaxf(mx1, __shfl_xor_sync(0xffffffffu, mx1, 2));

        float nm0 = fmaxf(m0, mx0), nm1 = fmaxf(m1, mx1);
        float corr0 = __expf(m0 - nm0), corr1 = __expf(m1 - nm1);
        m0 = nm0;
        m1 = nm1;

        float sum0 = 0.f, sum1 = 0.f;
#pragma unroll
        for (int nt = 0; nt < 8; nt++) {
            float p0 = __expf(S[nt][0] - m0);
            float p1 = __expf(S[nt][1] - m0);
            float p2 = __expf(S[nt][2] - m1);
            float p3 = __expf(S[nt][3] - m1);
            S[nt][0] = p0;
            S[nt][1] = p1;
            S[nt][2] = p2;
            S[nt][3] = p3;
            sum0 += p0 + p1;
            sum1 += p2 + p3;
        }
        sum0 += __shfl_xor_sync(0xffffffffu, sum0, 1);
        sum0 += __shfl_xor_sync(0xffffffffu, sum0, 2);
        sum1 += __shfl_xor_sync(0xffffffffu, sum1, 1);
        sum1 += __shfl_xor_sync(0xffffffffu, sum1, 2);
        l0 = l0 * corr0 + sum0;
        l1 = l1 * corr1 + sum1;

#pragma unroll
        for (int dt = 0; dt < 8; dt++) {
            O[dt][0] *= corr0;
            O[dt][1] *= corr0;
            O[dt][2] *= corr1;
            O[dt][3] *= corr1;
        }

#pragma unroll
        for (int kc2 = 0; kc2 < 4; kc2++) {
            uint32_t aP[4];
            aP[0] = packh2(S[2 * kc2][0], S[2 * kc2][1]);
            aP[1] = packh2(S[2 * kc2][2], S[2 * kc2][3]);
            aP[2] = packh2(S[2 * kc2 + 1][0], S[2 * kc2 + 1][1]);
            aP[3] = packh2(S[2 * kc2 + 1][2], S[2 * kc2 + 1][3]);
            uint32_t vrow = (uint32_t)(kc2 * 16) + vrowlocal;
            uint32_t vra = vbase + vrow * 128;
            uint32_t vswz = vrow & 7;
#pragma unroll
            for (int cc = 0; cc < 4; cc++) {
                uint32_t v0, v1, v2, v3;
                LDSM_X4_T(v0, v1, v2, v3,
                          vra + (((uint32_t)((2 * cc + vcbit) ^ vswz)) << 4));
                uint32_t bA[2] = {v0, v1}, bB[2] = {v2, v3};
                MMA_FP16(O[2 * cc], aP, bA);
                MMA_FP16(O[2 * cc + 1], aP, bB);
            }
        }
        __syncthreads();
    }

    float i0 = 1.0f / l0, i1 = 1.0f / l1;
    __half* o0 = out + (size_t)(b * Nn + row0) * EMB + h * DH + kq * 2;
    __half* o1 = out + (size_t)(b * Nn + row1) * EMB + h * DH + kq * 2;
#pragma unroll
    for (int dt = 0; dt < 8; dt++) {
        *(__half2*)(o0 + dt * 8) =
            __floats2half2_rn(O[dt][0] * i0, O[dt][1] * i0);
        *(__half2*)(o1 + dt * 8) =
            __floats2half2_rn(O[dt][2] * i1, O[dt][3] * i1);
    }
}

// ---------------- host orchestration -----------------------------------------
extern "C" void kernel_launch(void* const* d_in, const int* in_sizes, int n_in,
                              void* d_out, int out_size) {
    const float* x = (const float*)d_in[0];
    const float* wqkv = (const float*)d_in[1];
    const float* bqkv = (const float*)d_in[2];
    const float* wo = (const float*)d_in[3];
    const float* bo = (const float*)d_in[4];
    const float* ln1s = (const float*)d_in[5];
    const float* ln1b = (const float*)d_in[6];
    const float* ln2s = (const float*)d_in[7];
    const float* ln2b = (const float*)d_in[8];
    const float* w1 = (const float*)d_in[9];
    const float* w2 = (const float*)d_in[10];
    const float* lnfs = (const float*)d_in[11];
    const float* lnfb = (const float*)d_in[12];
    float* out = (float*)d_out;

    float* p_h;
    __half *p_y, *p_qkv, *p_o, *p_mid, *p_wqkv, *p_wo, *p_w1, *p_w2;
    cudaGetSymbolAddress((void**)&p_h, g_h);
    cudaGetSymbolAddress((void**)&p_y, g_y);
    cudaGetSymbolAddress((void**)&p_qkv, g_qkv);
    cudaGetSymbolAddress((void**)&p_o, g_o);
    cudaGetSymbolAddress((void**)&p_mid, g_mid);
    cudaGetSymbolAddress((void**)&p_wqkv, g_wqkv);
    cudaGetSymbolAddress((void**)&p_wo, g_wo);
    cudaGetSymbolAddress((void**)&p_w1, g_w1);
    cudaGetSymbolAddress((void**)&p_w2, g_w2);

    cudaFuncSetAttribute(gemm_fp16<64>,
                         cudaFuncAttributeMaxDynamicSharedMemorySize,
                         GEMM_SMEM_64);
    cudaFuncSetAttribute(gemm_fp16<128>,
                         cudaFuncAttributeMaxDynamicSharedMemorySize,
                         GEMM_SMEM_128);

    copy_kernel<<<(TOK * EMB + 255) / 256, 256>>>(x);

    transpose_half_all<<<TALL, dim3(32, 8)>>>(wqkv, wo, w1, w2, p_wqkv, p_wo,
                                              p_w1, p_w2);

    for (int L = 0; L < DEPTH; L++) {
        ln_kernel<<<TOK, 256>>>(p_h, ln1s + L * EMB, ln1b + L * EMB, p_y, 1);
        {  // qkv = y @ Wqkv + b (fp16 out) : BN=128
            dim3 grid(3 * EMB / 128, TOK / 128);
            gemm_fp16<128><<<grid, 128, GEMM_SMEM_128>>>(
                p_y, p_wqkv + (size_t)L * EMB * 3 * EMB, bqkv + L * 3 * EMB,
                p_qkv, EMB, 3 * EMB, FLAG_BIAS | FLAG_HALF);
        }
        {  // flash attention
            dim3 grid(Nn / 64, Bb * NH);
            attn_mma<<<grid, 128>>>(p_qkv, p_o);
        }
        {  // h += o @ Wo + bo : BN=64
            dim3 grid(EMB / 64, TOK / 128);
            gemm_fp16<64><<<grid, 128, GEMM_SMEM_64>>>(
                p_o, p_wo + (size_t)L * EMB * EMB, bo + L * EMB, p_h, EMB, EMB,
                FLAG_BIAS | FLAG_ADD);
        }
        ln_kernel<<<TOK, 256>>>(p_h, ln2s + L * EMB, ln2b + L * EMB, p_y, 1);
        {  // mid = gelu(y @ W1) : BN=128
            dim3 grid(FF / 128, TOK / 128);
            gemm_fp16<128><<<grid, 128, GEMM_SMEM_128>>>(
                p_y, p_w1 + (size_t)L * EMB * FF, nullptr, p_mid, EMB, FF,
                FLAG_GELU | FLAG_HALF);
        }
        {  // h += mid @ W2 : BN=64
            dim3 grid(EMB / 64, TOK / 128);
            gemm_fp16<64><<<grid, 128, GEMM_SMEM_64>>>(
                p_mid, p_w2 + (size_t)L * FF * EMB, nullptr, p_h, FF, EMB,
                FLAG_ADD);
        }
    }

    ln_kernel<<<TOK, 256>>>(p_h, lnfs, lnfb, out, 0);
}

// round 12
// speedup vs baseline: 6.2604x; 1.1474x over previous
#include <cuda_runtime.h>
#include <cuda_fp16.h>
#include <math.h>
#include <stdint.h>

#define Bb 2
#define Nn 2048
#define EMB 768
#define NH 12
#define DH 64
#define DEPTH 6
#define FF 3072
#define TOK (Bb * Nn)  // 4096
#define QKVW (3 * EMB) // 2304
#define LN_EPS 1e-6f

// ---------------- scratch (static device globals) ---------------------------
__device__ float g_h[TOK * EMB];
__device__ __half g_y[TOK * EMB];
__device__ __half g_qkv[TOK * 3 * EMB];
__device__ __half g_o[TOK * EMB];
__device__ __half g_mid[TOK * FF];
__device__ __half g_wqkv[DEPTH * EMB * 3 * EMB];
__device__ __half g_wo[DEPTH * EMB * EMB];
__device__ __half g_w1[DEPTH * EMB * FF];
__device__ __half g_w2[DEPTH * FF * EMB];

__constant__ float c_slopes[NH] = {
    0.5f, 0.25f, 0.125f, 0.0625f, 0.03125f, 0.015625f, 0.0078125f, 0.00390625f,
    0.70710678118654752f, 0.35355339059327376f, 0.17677669529663688f,
    0.08838834764831844f};

__device__ __forceinline__ void cp16(uint32_t dst, const void* src) {
    asm volatile("cp.async.cg.shared.global [%0], [%1], 16;" ::"r"(dst),
                 "l"(src));
}

__device__ __forceinline__ uint32_t packh2(float a, float b) {
    __half2 h = __floats2half2_rn(a, b);
    return *(uint32_t*)&h;
}

#define MMA_FP16(d, a, b)                                                     \
    asm volatile(                                                             \
        "mma.sync.aligned.m16n8k16.row.col.f32.f16.f16.f32 "                  \
        "{%0,%1,%2,%3},{%4,%5,%6,%7},{%8,%9},{%0,%1,%2,%3};"                  \
        : "+f"(d[0]), "+f"(d[1]), "+f"(d[2]), "+f"(d[3])                      \
        : "r"(a[0]), "r"(a[1]), "r"(a[2]), "r"(a[3]), "r"(b[0]), "r"(b[1]))

#define LDSM_X4(r0, r1, r2, r3, addr)                                        \
    asm volatile(                                                            \
        "ldmatrix.sync.aligned.m8n8.x4.shared.b16 {%0,%1,%2,%3}, [%4];"      \
        : "=r"(r0), "=r"(r1), "=r"(r2), "=r"(r3)                             \
        : "r"(addr))

#define LDSM_X4_T(r0, r1, r2, r3, addr)                                      \
    asm volatile(                                                            \
        "ldmatrix.sync.aligned.m8n8.x4.trans.shared.b16 {%0,%1,%2,%3}, "     \
        "[%4];"                                                              \
        : "=r"(r0), "=r"(r1), "=r"(r2), "=r"(r3)                             \
        : "r"(addr))

// ---------------- copy x -> h ------------------------------------------------
__global__ void copy_kernel(const float* __restrict__ x) {
    int i = blockIdx.x * blockDim.x + threadIdx.x;
    if (i < TOK * EMB) g_h[i] = x[i];
}

// ---------------- fused transpose + fp16 convert of ALL weights -------------
#define TQKV (72 * 24 * DEPTH)
#define TWO (24 * 24 * DEPTH)
#define TW1 (96 * 24 * DEPTH)
#define TW2 (24 * 96 * DEPTH)
#define TALL (TQKV + TWO + TW1 + TW2)

__global__ void transpose_half_all(const float* __restrict__ wqkv,
                                   const float* __restrict__ wo,
                                   const float* __restrict__ w1,
                                   const float* __restrict__ w2,
                                   __half* __restrict__ pwqkv,
                                   __half* __restrict__ pwo,
                                   __half* __restrict__ pw1,
                                   __half* __restrict__ pw2) {
    __shared__ float tile[32][33];
    int b = blockIdx.x;
    const float* W;
    __half* Wt;
    int K, N;
    if (b < TQKV) {
        W = wqkv; Wt = pwqkv; K = EMB; N = 3 * EMB;
    } else if (b < TQKV + TWO) {
        b -= TQKV; W = wo; Wt = pwo; K = EMB; N = EMB;
    } else if (b < TQKV + TWO + TW1) {
        b -= TQKV + TWO; W = w1; Wt = pw1; K = EMB; N = FF;
    } else {
        b -= TQKV + TWO + TW1; W = w2; Wt = pw2; K = FF; N = EMB;
    }
    int ntiles = N / 32, tpl = ntiles * (K / 32);
    int layer = b / tpl, rem = b % tpl;
    int bn = (rem % ntiles) * 32, bk = (rem / ntiles) * 32;
    W += (size_t)layer * K * N;
    Wt += (size_t)layer * K * N;
    int tx = threadIdx.x, ty = threadIdx.y;
#pragma unroll
    for (int i = 0; i < 32; i += 8)
        tile[ty + i][tx] = W[(size_t)(bk + ty + i) * N + bn + tx];
    __syncthreads();
#pragma unroll
    for (int i = 0; i < 32; i += 8)
        Wt[(size_t)(bn + ty + i) * K + bk + tx] =
            __float2half_rn(tile[tx][ty + i]);
}

// ---------------- LayerNorm (float in; float or half out) -------------------
__global__ void ln_kernel(const float* __restrict__ in,
                          const float* __restrict__ scale,
                          const float* __restrict__ bias, void* __restrict__ o,
                          int half_out) {
    int row = blockIdx.x;
    const float* p = in + (size_t)row * EMB;
    float s = 0.f, ss = 0.f;
    for (int i = threadIdx.x; i < EMB; i += 256) {
        float v = p[i];
        s += v;
        ss += v * v;
    }
#pragma unroll
    for (int of = 16; of; of >>= 1) {
        s += __shfl_xor_sync(0xffffffffu, s, of);
        ss += __shfl_xor_sync(0xffffffffu, ss, of);
    }
    __shared__ float sh_s[8], sh_ss[8];
    int w = threadIdx.x >> 5, lane = threadIdx.x & 31;
    if (lane == 0) { sh_s[w] = s; sh_ss[w] = ss; }
    __syncthreads();
    if (threadIdx.x < 32) {
        s = (lane < 8) ? sh_s[lane] : 0.f;
        ss = (lane < 8) ? sh_ss[lane] : 0.f;
#pragma unroll
        for (int of = 4; of; of >>= 1) {
            s += __shfl_xor_sync(0xffffffffu, s, of);
            ss += __shfl_xor_sync(0xffffffffu, ss, of);
        }
        if (lane == 0) { sh_s[0] = s; sh_ss[0] = ss; }
    }
    __syncthreads();
    float mean = sh_s[0] * (1.0f / EMB);
    float var = sh_ss[0] * (1.0f / EMB) - mean * mean;
    float inv = rsqrtf(var + LN_EPS);
    if (half_out) {
        __half* q = (__half*)o + (size_t)row * EMB;
        for (int i = threadIdx.x; i < EMB; i += 256)
            q[i] = __float2half_rn((p[i] - mean) * inv * scale[i] + bias[i]);
    } else {
        float* q = (float*)o + (size_t)row * EMB;
        for (int i = threadIdx.x; i < EMB; i += 256)
            q[i] = (p[i] - mean) * inv * scale[i] + bias[i];
    }
}

#define FLAG_BIAS 1
#define FLAG_GELU 2
#define FLAG_ADD 4
#define FLAG_HALF 8

#define STAGES 4
#define A_STAGE 8192

__device__ __forceinline__ float gelu_tanh(float x) {
    const float k0 = 0.7978845608028654f;
    return 0.5f * x * (1.0f + tanhf(k0 * (x + 0.044715f * x * x * x)));
}

// ---------------- fp16 GEMM, CTA 128x64, 128 thr, 4 CTA/SM ------------------
__global__ __launch_bounds__(128, 4) void gemm64(
    const __half* __restrict__ A, const __half* __restrict__ Wt,
    const float* __restrict__ bias, void* __restrict__ Cv, int K, int Nout,
    int flags) {
    constexpr int B_STAGE = 64 * 64;
    constexpr int STAGE_BYTES = A_STAGE + B_STAGE;

    extern __shared__ char smem[];
    const uint32_t sb = (uint32_t)__cvta_generic_to_shared(smem);
    const int tid = threadIdx.x;
    const int warp = tid >> 5, lane = tid & 31;
    const int wm = warp >> 1, wn = warp & 1;
    const int bm = blockIdx.y * 128, bn = blockIdx.x * 64;

    const __half* gA = A + (size_t)(bm + tid) * K;
    uint32_t stA[4];
#pragma unroll
    for (int c = 0; c < 4; c++)
        stA[c] = sb + (uint32_t)tid * 64 +
                 (((uint32_t)(c ^ ((tid >> 1) & 3))) << 4);
    const int brow = tid >> 1, bc0 = (tid & 1) * 2;
    const __half* gB = Wt + (size_t)(bn + brow) * K + bc0 * 8;
    uint32_t stB[2];
#pragma unroll
    for (int i = 0; i < 2; i++)
        stB[i] = sb + A_STAGE + (uint32_t)brow * 64 +
                 (((uint32_t)((bc0 + i) ^ ((brow >> 1) & 3))) << 4);

#define LOAD_STAGE64(s, t_)                                                \
    do {                                                                   \
        const __half* _a = gA + (t_) * 32;                                 \
        const __half* _b = gB + (t_) * 32;                                 \
        uint32_t _so = (uint32_t)(s)*STAGE_BYTES;                          \
        _Pragma("unroll") for (int _c = 0; _c < 4; _c++)                   \
            cp16(stA[_c] + _so, _a + _c * 8);                              \
        _Pragma("unroll") for (int _i = 0; _i < 2; _i++)                   \
            cp16(stB[_i] + _so, _b + _i * 8);                              \
        asm volatile("cp.async.commit_group;");                            \
    } while (0)

    int arow7 = lane & 7;
    int a8 = ((lane >> 3) & 1) * 8;
    int acbit = lane >> 4;
    int axor = (arow7 >> 1) & 3;
    uint32_t aBase[4];
#pragma unroll
    for (int mf = 0; mf < 4; mf++) {
        int r = wm * 64 + mf * 16 + arow7 + a8;
        aBase[mf] = sb + (uint32_t)r * 64;
    }
    uint32_t aoff[2];
#pragma unroll
    for (int ks = 0; ks < 2; ks++)
        aoff[ks] = ((uint32_t)((2 * ks + acbit) ^ axor)) << 4;

    int brow7 = lane & 7;
    int bn8 = (lane >> 4) * 8;
    int bcb = (lane >> 3) & 1;
    int bxor = (brow7 >> 1) & 3;
    uint32_t bBase[2];
#pragma unroll
    for (int p = 0; p < 2; p++) {
        int r = wn * 32 + p * 16 + brow7 + bn8;
        bBase[p] = sb + A_STAGE + (uint32_t)r * 64;
    }
    uint32_t boff[2];
#pragma unroll
    for (int ks = 0; ks < 2; ks++)
        boff[ks] = ((uint32_t)((2 * ks + bcb) ^ bxor)) << 4;

    float acc[4][4][4];
#pragma unroll
    for (int i = 0; i < 4; i++)
#pragma unroll
        for (int j = 0; j < 4; j++)
#pragma unroll
            for (int c = 0; c < 4; c++) acc[i][j][c] = 0.f;

    const int T = K / 32;
    LOAD_STAGE64(0, 0);
    LOAD_STAGE64(1, 1);
    LOAD_STAGE64(2, 2);

    for (int t = 0; t < T; t++) {
        int rem = ((t + 2 < T) ? (t + 2) : (T - 1)) - t;
        if (rem == 2)
            asm volatile("cp.async.wait_group 2;");
        else if (rem == 1)
            asm volatile("cp.async.wait_group 1;");
        else
            asm volatile("cp.async.wait_group 0;");
        __syncthreads();
        if (t + 3 < T) LOAD_STAGE64((t + 3) & 3, t + 3);

        uint32_t so = (uint32_t)(t & 3) * STAGE_BYTES;
#pragma unroll
        for (int ks = 0; ks < 2; ks++) {
            uint32_t af[4][4];
#pragma unroll
            for (int mf = 0; mf < 4; mf++)
                LDSM_X4(af[mf][0], af[mf][1], af[mf][2], af[mf][3],
                        aBase[mf] + so + aoff[ks]);
#pragma unroll
            for (int p = 0; p < 2; p++) {
                uint32_t bf0[2], bf1[2];
                LDSM_X4(bf0[0], bf0[1], bf1[0], bf1[1],
                        bBase[p] + so + boff[ks]);
#pragma unroll
                for (int mf = 0; mf < 4; mf++) {
                    MMA_FP16(acc[mf][2 * p], af[mf], bf0);
                    MMA_FP16(acc[mf][2 * p + 1], af[mf], bf1);
                }
            }
        }
    }

    int r = lane >> 2, kq = lane & 3;
#pragma unroll
    for (int mf = 0; mf < 4; mf++) {
#pragma unroll
        for (int nf = 0; nf < 4; nf++) {
            int n0 = bn + wn * 32 + nf * 8 + kq * 2;
#pragma unroll
            for (int half = 0; half < 2; half++) {
                int m0 = bm + wm * 64 + mf * 16 + r + half * 8;
                float2 v;
                v.x = acc[mf][nf][half * 2 + 0];
                v.y = acc[mf][nf][half * 2 + 1];
                if (flags & FLAG_BIAS) {
                    v.x += bias[n0];
                    v.y += bias[n0 + 1];
                }
                if (flags & FLAG_GELU) {
                    v.x = gelu_tanh(v.x);
                    v.y = gelu_tanh(v.y);
                }
                if (flags & FLAG_HALF) {
                    __half2* dst =
                        (__half2*)((__half*)Cv + (size_t)m0 * Nout + n0);
                    *dst = __floats2half2_rn(v.x, v.y);
                } else {
                    float2* dst =
                        (float2*)((float*)Cv + (size_t)m0 * Nout + n0);
                    if (flags & FLAG_ADD) {
                        float2 old = *dst;
                        v.x += old.x;
                        v.y += old.y;
                    }
                    *dst = v;
                }
            }
        }
    }
}
#define GEMM_SMEM_64 (STAGES * (A_STAGE + 64 * 64))

// ---------------- fp16 GEMM, CTA 128x128, 256 thr (8 warps), 2 CTA/SM -------
// warp tile 64x32 (2m x 4n) -> acc 64 regs, no spill.
__global__ __launch_bounds__(256, 2) void gemm128(
    const __half* __restrict__ A, const __half* __restrict__ Wt,
    const float* __restrict__ bias, void* __restrict__ Cv, int K, int Nout,
    int flags) {
    constexpr int B_STAGE = 128 * 64;
    constexpr int STAGE_BYTES = A_STAGE + B_STAGE;  // 16KB

    extern __shared__ char smem[];
    const uint32_t sb = (uint32_t)__cvta_generic_to_shared(smem);
    const int tid = threadIdx.x;
    const int warp = tid >> 5, lane = tid & 31;
    const int wm = warp >> 2, wn = warp & 3;  // 2m x 4n
    const int bm = blockIdx.y * 128, bn = blockIdx.x * 128;

    // staging: 256 threads; A row tid>>1 (2 chunks), B row tid>>1 (2 chunks)
    const int srow = tid >> 1, sc0 = (tid & 1) * 2;
    const __half* gA = A + (size_t)(bm + srow) * K + sc0 * 8;
    const __half* gB = Wt + (size_t)(bn + srow) * K + sc0 * 8;
    uint32_t stA[2], stB[2];
#pragma unroll
    for (int i = 0; i < 2; i++) {
        uint32_t off = (uint32_t)srow * 64 +
                       (((uint32_t)((sc0 + i) ^ ((srow >> 1) & 3))) << 4);
        stA[i] = sb + off;
        stB[i] = sb + A_STAGE + off;
    }

#define LOAD_STAGE128(s, t_)                                               \
    do {                                                                   \
        const __half* _a = gA + (t_) * 32;                                 \
        const __half* _b = gB + (t_) * 32;                                 \
        uint32_t _so = (uint32_t)(s)*STAGE_BYTES;                          \
        _Pragma("unroll") for (int _i = 0; _i < 2; _i++) {                 \
            cp16(stA[_i] + _so, _a + _i * 8);                              \
            cp16(stB[_i] + _so, _b + _i * 8);                              \
        }                                                                  \
        asm volatile("cp.async.commit_group;");                            \
    } while (0)

    int arow7 = lane & 7;
    int a8 = ((lane >> 3) & 1) * 8;
    int acbit = lane >> 4;
    int axor = (arow7 >> 1) & 3;
    uint32_t aBase[4];
#pragma unroll
    for (int mf = 0; mf < 4; mf++) {
        int r = wm * 64 + mf * 16 + arow7 + a8;
        aBase[mf] = sb + (uint32_t)r * 64;
    }
    uint32_t aoff[2];
#pragma unroll
    for (int ks = 0; ks < 2; ks++)
        aoff[ks] = ((uint32_t)((2 * ks + acbit) ^ axor)) << 4;

    int brow7 = lane & 7;
    int bn8 = (lane >> 4) * 8;
    int bcb = (lane >> 3) & 1;
    int bxor = (brow7 >> 1) & 3;
    uint32_t bBase[2];
#pragma unroll
    for (int p = 0; p < 2; p++) {
        int r = wn * 32 + p * 16 + brow7 + bn8;
        bBase[p] = sb + A_STAGE + (uint32_t)r * 64;
    }
    uint32_t boff[2];
#pragma unroll
    for (int ks = 0; ks < 2; ks++)
        boff[ks] = ((uint32_t)((2 * ks + bcb) ^ bxor)) << 4;

    float acc[4][4][4];
#pragma unroll
    for (int i = 0; i < 4; i++)
#pragma unroll
        for (int j = 0; j < 4; j++)
#pragma unroll
            for (int c = 0; c < 4; c++) acc[i][j][c] = 0.f;

    const int T = K / 32;
    LOAD_STAGE128(0, 0);
    LOAD_STAGE128(1, 1);
    LOAD_STAGE128(2, 2);

    for (int t = 0; t < T; t++) {
        int rem = ((t + 2 < T) ? (t + 2) : (T - 1)) - t;
        if (rem == 2)
            asm volatile("cp.async.wait_group 2;");
        else if (rem == 1)
            asm volatile("cp.async.wait_group 1;");
        else
            asm volatile("cp.async.wait_group 0;");
        __syncthreads();
        if (t + 3 < T) LOAD_STAGE128((t + 3) & 3, t + 3);

        uint32_t so = (uint32_t)(t & 3) * STAGE_BYTES;
#pragma unroll
        for (int ks = 0; ks < 2; ks++) {
            uint32_t af[4][4];
#pragma unroll
            for (int mf = 0; mf < 4; mf++)
                LDSM_X4(af[mf][0], af[mf][1], af[mf][2], af[mf][3],
                        aBase[mf] + so + aoff[ks]);
#pragma unroll
            for (int p = 0; p < 2; p++) {
                uint32_t bf0[2], bf1[2];
                LDSM_X4(bf0[0], bf0[1], bf1[0], bf1[1],
                        bBase[p] + so + boff[ks]);
#pragma unroll
                for (int mf = 0; mf < 4; mf++) {
                    MMA_FP16(acc[mf][2 * p], af[mf], bf0);
                    MMA_FP16(acc[mf][2 * p + 1], af[mf], bf1);
                }
            }
        }
    }

    int r = lane >> 2, kq = lane & 3;
#pragma unroll
    for (int mf = 0; mf < 4; mf++) {
#pragma unroll
        for (int nf = 0; nf < 4; nf++) {
            int n0 = bn + wn * 32 + nf * 8 + kq * 2;
#pragma unroll
            for (int half = 0; half < 2; half++) {
                int m0 = bm + wm * 64 + mf * 16 + r + half * 8;
                float2 v;
                v.x = acc[mf][nf][half * 2 + 0];
                v.y = acc[mf][nf][half * 2 + 1];
                if (flags & FLAG_BIAS) {
                    v.x += bias[n0];
                    v.y += bias[n0 + 1];
                }
                if (flags & FLAG_GELU) {
                    v.x = gelu_tanh(v.x);
                    v.y = gelu_tanh(v.y);
                }
                if (flags & FLAG_HALF) {
                    __half2* dst =
                        (__half2*)((__half*)Cv + (size_t)m0 * Nout + n0);
                    *dst = __floats2half2_rn(v.x, v.y);
                } else {
                    float2* dst =
                        (float2*)((float*)Cv + (size_t)m0 * Nout + n0);
                    if (flags & FLAG_ADD) {
                        float2 old = *dst;
                        v.x += old.x;
                        v.y += old.y;
                    }
                    *dst = v;
                }
            }
        }
    }
}
#define GEMM_SMEM_128 (STAGES * (A_STAGE + 128 * 64))

// ---------------- flash attention w/ tensor cores (causal + ALiBi) ----------
__global__ __launch_bounds__(128) void attn_mma(const __half* __restrict__ qkv,
                                                __half* __restrict__ out) {
    __shared__ __align__(16) char smem[40960];
    const uint32_t sb = (uint32_t)__cvta_generic_to_shared(smem);
    const int tid = threadIdx.x;
    const int w = tid >> 5, lane = tid & 31;
    const int qt = blockIdx.x, bh = blockIdx.y;
    const int b = bh / NH, h = bh % NH;
    const float slope = c_slopes[h];

    const int srow = tid >> 1, c0 = (tid & 1) * 4;
    const int sxor = srow & 7;
    const uint32_t rowoff = sb + (uint32_t)srow * 128;

    {
        const __half* gQ = qkv +
                           (size_t)(b * Nn + qt * 64 + srow) * QKVW + h * DH +
                           c0 * 8;
#pragma unroll
        for (int i = 0; i < 4; i++)
            cp16(rowoff + (((uint32_t)((c0 + i) ^ sxor)) << 4), gQ + i * 8);
        asm volatile("cp.async.commit_group;");
    }

#define LOAD_KV(kt_, buf_)                                                   \
    do {                                                                     \
        const __half* _gK = qkv +                                            \
                            (size_t)(b * Nn + (kt_)*64 + srow) * QKVW + EMB + \
                            h * DH + c0 * 8;                                 \
        uint32_t _base = rowoff + 8192 + (uint32_t)(buf_)*16384;             \
        _Pragma("unroll") for (int _i = 0; _i < 4; _i++)                     \
            cp16(_base + (((uint32_t)((c0 + _i) ^ sxor)) << 4), _gK + _i * 8); \
        _Pragma("unroll") for (int _i = 0; _i < 4; _i++)                     \
            cp16(_base + 8192 + (((uint32_t)((c0 + _i) ^ sxor)) << 4),       \
                 _gK + EMB + _i * 8);                                        \
        asm volatile("cp.async.commit_group;");                              \
    } while (0)

    LOAD_KV(0, 0);

    asm volatile("cp.async.wait_group 1;");
    __syncthreads();
    const int arow7 = lane & 7;
    const int a8 = ((lane >> 3) & 1) * 8;
    const int acbit = lane >> 4;
    uint32_t Qf[4][4];
    {
        uint32_t qrow = (uint32_t)(w * 16 + arow7 + a8);
        uint32_t qaddr = sb + qrow * 128;
#pragma unroll
        for (int kc = 0; kc < 4; kc++)
            LDSM_X4(Qf[kc][0], Qf[kc][1], Qf[kc][2], Qf[kc][3],
                    qaddr + (((uint32_t)((2 * kc + acbit) ^ arow7)) << 4));
    }

    const int r = lane >> 2, kq = lane & 3;
    const int row0 = qt * 64 + w * 16 + r;
    const int row1 = row0 + 8;
    float m0 = -1e30f, m1 = -1e30f, l0 = 0.f, l1 = 0.f;
    float O[8][4];
#pragma unroll
    for (int dt = 0; dt < 8; dt++)
#pragma unroll
        for (int c = 0; c < 4; c++) O[dt][c] = 0.f;

    const int bg = lane >> 3;
    const int bcb = bg & 1;
    const int brofs = (bg >> 1) * 8;
    const int brow7 = lane & 7;
    const uint32_t vrowlocal = (uint32_t)((lane & 7) + ((lane >> 3) & 1) * 8);
    const int vcbit = lane >> 4;

    for (int kt = 0; kt <= qt; kt++) {
        int buf = kt & 1;
        if (kt < qt) LOAD_KV(kt + 1, buf ^ 1);
        if (kt < qt)
            asm volatile("cp.async.wait_group 1;");
        else
            asm volatile("cp.async.wait_group 0;");
        __syncthreads();

        uint32_t kbase = sb + 8192 + (uint32_t)buf * 16384;
        uint32_t vbase = kbase + 8192;

        float S[8][4];
#pragma unroll
        for (int nt = 0; nt < 8; nt++)
#pragma unroll
            for (int c = 0; c < 4; c++) S[nt][c] = 0.f;
#pragma unroll
        for (int kc = 0; kc < 4; kc++) {
            uint32_t bf[8][2];
#pragma unroll
            for (int p = 0; p < 4; p++) {
                uint32_t rr = (uint32_t)(p * 16 + brofs + brow7);
                LDSM_X4(bf[2 * p][0], bf[2 * p][1], bf[2 * p + 1][0],
                        bf[2 * p + 1][1],
                        kbase + rr * 128 +
                            (((uint32_t)((2 * kc + bcb) ^ brow7)) << 4));
            }
#pragma unroll
            for (int nt = 0; nt < 8; nt++) MMA_FP16(S[nt], Qf[kc], bf[nt]);
        }

        bool diag = (kt == qt);
        float mx0 = -1e30f, mx1 = -1e30f;
#pragma unroll
        for (int nt = 0; nt < 8; nt++) {
            int colb = kt * 64 + nt * 8 + kq * 2;
#pragma unroll
            for (int c = 0; c < 4; c++) {
                int col = colb + (c & 1);
                float v = S[nt][c] * 0.125f + slope * (float)col;
                if (diag && col > ((c < 2) ? row0 : row1)) v = -1e30f;
                S[nt][c] = v;
                if (c < 2)
                    mx0 = fmaxf(mx0, v);
                else
                    mx1 = fmaxf(mx1, v);
            }
        }
        mx0 = fmaxf(mx0, __shfl_xor_sync(0xffffffffu, mx0, 1));
        mx0 = fmaxf(mx0, __shfl_xor_sync(0xffffffffu, mx0, 2));
        mx1 = fmaxf(mx1, __shfl_xor_sync(0xffffffffu, mx1, 1));
        mx1 = fmaxf(mx1, __shfl_xor_sync(0xffffffffu, mx1, 2));

        float nm0 = fmaxf(m0, mx0), nm1 = fmaxf(m1, mx1);
        float corr0 = __expf(m0 - nm0), corr1 = __expf(m1 - nm1);
        m0 = nm0;
        m1 = nm1;

        float sum0 = 0.f, sum1 = 0.f;
#pragma unroll
        for (int nt = 0; nt < 8; nt++) {
            float p0 = __expf(S[nt][0] - m0);
            float p1 = __expf(S[nt][1] - m0);
            float p2 = __expf(S[nt][2] - m1);
            float p3 = __expf(S[nt][3] - m1);
            S[nt][0] = p0;
            S[nt][1] = p1;
            S[nt][2] = p2;
            S[nt][3] = p3;
            sum0 += p0 + p1;
            sum1 += p2 + p3;
        }
        sum0 += __shfl_xor_sync(0xffffffffu, sum0, 1);
        sum0 += __shfl_xor_sync(0xffffffffu, sum0, 2);
        sum1 += __shfl_xor_sync(0xffffffffu, sum1, 1);
        sum1 += __shfl_xor_sync(0xffffffffu, sum1, 2);
        l0 = l0 * corr0 + sum0;
        l1 = l1 * corr1 + sum1;

#pragma unroll
        for (int dt = 0; dt < 8; dt++) {
            O[dt][0] *= corr0;
            O[dt][1] *= corr0;
            O[dt][2] *= corr1;
            O[dt][3] *= corr1;
        }

#pragma unroll
        for (int kc2 = 0; kc2 < 4; kc2++) {
            uint32_t aP[4];
            aP[0] = packh2(S[2 * kc2][0], S[2 * kc2][1]);
            aP[1] = packh2(S[2 * kc2][2], S[2 * kc2][3]);
            aP[2] = packh2(S[2 * kc2 + 1][0], S[2 * kc2 + 1][1]);
            aP[3] = packh2(S[2 * kc2 + 1][2], S[2 * kc2 + 1][3]);
            uint32_t vrow = (uint32_t)(kc2 * 16) + vrowlocal;
            uint32_t vra = vbase + vrow * 128;
            uint32_t vswz = vrow & 7;
#pragma unroll
            for (int cc = 0; cc < 4; cc++) {
                uint32_t v0, v1, v2, v3;
                LDSM_X4_T(v0, v1, v2, v3,
                          vra + (((uint32_t)((2 * cc + vcbit) ^ vswz)) << 4));
                uint32_t bA[2] = {v0, v1}, bB[2] = {v2, v3};
                MMA_FP16(O[2 * cc], aP, bA);
                MMA_FP16(O[2 * cc + 1], aP, bB);
            }
        }
        __syncthreads();
    }

    float i0 = 1.0f / l0, i1 = 1.0f / l1;
    __half* o0 = out + (size_t)(b * Nn + row0) * EMB + h * DH + kq * 2;
    __half* o1 = out + (size_t)(b * Nn + row1) * EMB + h * DH + kq * 2;
#pragma unroll
    for (int dt = 0; dt < 8; dt++) {
        *(__half2*)(o0 + dt * 8) =
            __floats2half2_rn(O[dt][0] * i0, O[dt][1] * i0);
        *(__half2*)(o1 + dt * 8) =
            __floats2half2_rn(O[dt][2] * i1, O[dt][3] * i1);
    }
}

// ---------------- host orchestration -----------------------------------------
extern "C" void kernel_launch(void* const* d_in, const int* in_sizes, int n_in,
                              void* d_out, int out_size) {
    const float* x = (const float*)d_in[0];
    const float* wqkv = (const float*)d_in[1];
    const float* bqkv = (const float*)d_in[2];
    const float* wo = (const float*)d_in[3];
    const float* bo = (const float*)d_in[4];
    const float* ln1s = (const float*)d_in[5];
    const float* ln1b = (const float*)d_in[6];
    const float* ln2s = (const float*)d_in[7];
    const float* ln2b = (const float*)d_in[8];
    const float* w1 = (const float*)d_in[9];
    const float* w2 = (const float*)d_in[10];
    const float* lnfs = (const float*)d_in[11];
    const float* lnfb = (const float*)d_in[12];
    float* out = (float*)d_out;

    float* p_h;
    __half *p_y, *p_qkv, *p_o, *p_mid, *p_wqkv, *p_wo, *p_w1, *p_w2;
    cudaGetSymbolAddress((void**)&p_h, g_h);
    cudaGetSymbolAddress((void**)&p_y, g_y);
    cudaGetSymbolAddress((void**)&p_qkv, g_qkv);
    cudaGetSymbolAddress((void**)&p_o, g_o);
    cudaGetSymbolAddress((void**)&p_mid, g_mid);
    cudaGetSymbolAddress((void**)&p_wqkv, g_wqkv);
    cudaGetSymbolAddress((void**)&p_wo, g_wo);
    cudaGetSymbolAddress((void**)&p_w1, g_w1);
    cudaGetSymbolAddress((void**)&p_w2, g_w2);

    cudaFuncSetAttribute(gemm64, cudaFuncAttributeMaxDynamicSharedMemorySize,
                         GEMM_SMEM_64);
    cudaFuncSetAttribute(gemm128, cudaFuncAttributeMaxDynamicSharedMemorySize,
                         GEMM_SMEM_128);

    copy_kernel<<<(TOK * EMB + 255) / 256, 256>>>(x);

    transpose_half_all<<<TALL, dim3(32, 8)>>>(wqkv, wo, w1, w2, p_wqkv, p_wo,
                                              p_w1, p_w2);

    for (int L = 0; L < DEPTH; L++) {
        ln_kernel<<<TOK, 256>>>(p_h, ln1s + L * EMB, ln1b + L * EMB, p_y, 1);
        {  // qkv = y @ Wqkv + b (fp16 out)
            dim3 grid(3 * EMB / 128, TOK / 128);
            gemm128<<<grid, 256, GEMM_SMEM_128>>>(
                p_y, p_wqkv + (size_t)L * EMB * 3 * EMB, bqkv + L * 3 * EMB,
                p_qkv, EMB, 3 * EMB, FLAG_BIAS | FLAG_HALF);
        }
        {  // flash attention
            dim3 grid(Nn / 64, Bb * NH);
            attn_mma<<<grid, 128>>>(p_qkv, p_o);
        }
        {  // h += o @ Wo + bo
            dim3 grid(EMB / 64, TOK / 128);
            gemm64<<<grid, 128, GEMM_SMEM_64>>>(
                p_o, p_wo + (size_t)L * EMB * EMB, bo + L * EMB, p_h, EMB, EMB,
                FLAG_BIAS | FLAG_ADD);
        }
        ln_kernel<<<TOK, 256>>>(p_h, ln2s + L * EMB, ln2b + L * EMB, p_y, 1);
        {  // mid = gelu(y @ W1) (half out)
            dim3 grid(FF / 128, TOK / 128);
            gemm128<<<grid, 256, GEMM_SMEM_128>>>(
                p_y, p_w1 + (size_t)L * EMB * FF, nullptr, p_mid, EMB, FF,
                FLAG_GELU | FLAG_HALF);
        }
        {  // h += mid @ W2
            dim3 grid(EMB / 64, TOK / 128);
            gemm64<<<grid, 128, GEMM_SMEM_64>>>(
                p_mid, p_w2 + (size_t)L * FF * EMB, nullptr, p_h, FF, EMB,
                FLAG_ADD);
        }
    }

    ln_kernel<<<TOK, 256>>>(p_h, lnfs, lnfb, out, 0);
}